// round 2
// baseline (speedup 1.0000x reference)
#include <cuda_runtime.h>
#include <math.h>

#define BB 16
#define SS 1025
#define HH 384
#define NHH 6
#define LL 12
#define II 1536
#define NCC 1000
#define MTOK (BB*SS)          // 16400
#define NPATCH 1024
#define MPATCH (BB*NPATCH)    // 16384

// Scratch (allocation-free rule: __device__ globals)
__device__ float g_h[MTOK*HH];
__device__ float g_hn[MTOK*HH];
__device__ float g_q[MTOK*HH];
__device__ float g_k[MTOK*HH];
__device__ float g_v[MTOK*HH];
__device__ float g_attn[MTOK*HH];
__device__ float g_mlp[MTOK*II];
__device__ float g_scores[BB*NHH*SS*SS];   // 403 MB

// ---------------------------------------------------------------------------
// Patch embed: im2col-on-the-fly GEMM. M=16384 (b,patch), N=384, K=768.
// C[m,o] = sum_k x_patch[m,k] * conv_w[o,k]; writes h[b, 1+pi, o] (+bias+pos)
// ---------------------------------------------------------------------------
__global__ void patch_embed_kernel(const float* __restrict__ x,
                                   const float* __restrict__ cw,
                                   const float* __restrict__ cb,
                                   const float* __restrict__ pos,
                                   float* __restrict__ h)
{
    __shared__ __align__(16) float As[16][68];
    __shared__ __align__(16) float Bs[16][68];
    int tx = threadIdx.x, ty = threadIdx.y;
    int t = ty * 16 + tx;
    int n0 = blockIdx.x * 64;
    int m0 = blockIdx.y * 64;
    float acc[4][4] = {};

    for (int k0 = 0; k0 < 768; k0 += 16) {
#pragma unroll
        for (int r = 0; r < 4; r++) {
            int idx = t + r * 256;
            int m = idx >> 4, kk = idx & 15;
            int k = k0 + kk;
            // A: gathered patch pixel
            int mg = m0 + m;
            int b = mg >> 10, pi = mg & 1023;
            int i = pi >> 5, j = pi & 31;
            int c = k >> 8, rr = (k >> 4) & 15, qq = k & 15;
            As[kk][m] = x[((b * 3 + c) * 512 + i * 16 + rr) * 512 + j * 16 + qq];
            // B: conv_w[o][k]
            Bs[kk][m] = cw[(n0 + m) * 768 + k];
        }
        __syncthreads();
#pragma unroll
        for (int kk = 0; kk < 16; kk++) {
            float4 af = *(const float4*)(&As[kk][ty * 4]);
            float4 bf = *(const float4*)(&Bs[kk][tx * 4]);
            float av[4] = {af.x, af.y, af.z, af.w};
            float bv[4] = {bf.x, bf.y, bf.z, bf.w};
#pragma unroll
            for (int i = 0; i < 4; i++)
#pragma unroll
                for (int j = 0; j < 4; j++) acc[i][j] += av[i] * bv[j];
        }
        __syncthreads();
    }
#pragma unroll
    for (int i = 0; i < 4; i++) {
        int mg = m0 + ty * 4 + i;
        int b = mg >> 10, pi = mg & 1023;
        int row = b * SS + 1 + pi;
#pragma unroll
        for (int j = 0; j < 4; j++) {
            int o = n0 + tx * 4 + j;
            h[row * HH + o] = acc[i][j] + cb[o] + pos[(1 + pi) * HH + o];
        }
    }
}

__global__ void cls_pos_kernel(const float* __restrict__ cls,
                               const float* __restrict__ pos,
                               float* __restrict__ h)
{
    int t = blockIdx.x * 256 + threadIdx.x;
    if (t < BB * HH) {
        int b = t / HH, o = t % HH;
        h[(b * SS) * HH + o] = cls[o] + pos[o];
    }
}

// ---------------------------------------------------------------------------
// LayerNorm over H=384. One 128-thread block per row, two-pass.
// ---------------------------------------------------------------------------
__global__ void ln_kernel(const float* __restrict__ in,
                          const float* __restrict__ w,
                          const float* __restrict__ b,
                          float* __restrict__ out)
{
    int row = blockIdx.x;
    const float* p = in + (size_t)row * HH;
    int t = threadIdx.x;            // 128 threads
    float v0 = p[t], v1 = p[t + 128], v2 = p[t + 256];

    __shared__ float sh[4];
    float s = v0 + v1 + v2;
#pragma unroll
    for (int o = 16; o; o >>= 1) s += __shfl_xor_sync(0xffffffffu, s, o);
    if ((t & 31) == 0) sh[t >> 5] = s;
    __syncthreads();
    float mu = (sh[0] + sh[1] + sh[2] + sh[3]) * (1.0f / 384.0f);
    __syncthreads();

    float d0 = v0 - mu, d1 = v1 - mu, d2 = v2 - mu;
    float sq = d0 * d0 + d1 * d1 + d2 * d2;
#pragma unroll
    for (int o = 16; o; o >>= 1) sq += __shfl_xor_sync(0xffffffffu, sq, o);
    if ((t & 31) == 0) sh[t >> 5] = sq;
    __syncthreads();
    float var = (sh[0] + sh[1] + sh[2] + sh[3]) * (1.0f / 384.0f);
    float inv = rsqrtf(var + 1e-5f);

    float* q = out + (size_t)row * HH;
    q[t]       = d0 * inv * w[t]       + b[t];
    q[t + 128] = d1 * inv * w[t + 128] + b[t + 128];
    q[t + 256] = d2 * inv * w[t + 256] + b[t + 256];
}

// ---------------------------------------------------------------------------
// Generic GEMM: C[M,N] = A[M,K] @ W[K,N] + bias, with epilogue variants.
// EPI 0: bias; 1: bias + residual (C += old C); 2: bias + GELU(tanh)
// Requires K%16==0, N%64==0. 64x64 tiles, 4x4 per thread.
// ---------------------------------------------------------------------------
__device__ __forceinline__ float gelu_f(float u)
{
    // tanh(x) = (1 - e^{-2x}) / (1 + e^{-2x})
    float a = -1.5957691216057308f * (u + 0.044715f * u * u * u);   // -2*c*(...)
    float e = __expf(fminf(a, 80.0f));
    float th = (1.0f - e) / (1.0f + e);
    return 0.5f * u * (1.0f + th);
}

template <int EPI>
__global__ void gemm_kernel(const float* __restrict__ A,
                            const float* __restrict__ W,
                            const float* __restrict__ bias,
                            float* __restrict__ C,
                            int M, int N, int K)
{
    __shared__ __align__(16) float As[16][68];
    __shared__ __align__(16) float Bs[16][64];
    int tx = threadIdx.x, ty = threadIdx.y;
    int t = ty * 16 + tx;
    int n0 = blockIdx.x * 64;
    int m0 = blockIdx.y * 64;
    float acc[4][4] = {};

    for (int k0 = 0; k0 < K; k0 += 16) {
#pragma unroll
        for (int r = 0; r < 4; r++) {
            int idx = t + r * 256;
            int m = idx >> 4, kk = idx & 15;
            int mg = m0 + m;
            As[kk][m] = (mg < M) ? A[(size_t)mg * K + k0 + kk] : 0.0f;
            int kb = idx >> 6, nb = idx & 63;
            Bs[kb][nb] = W[(size_t)(k0 + kb) * N + n0 + nb];
        }
        __syncthreads();
#pragma unroll
        for (int kk = 0; kk < 16; kk++) {
            float4 af = *(const float4*)(&As[kk][ty * 4]);
            float4 bf = *(const float4*)(&Bs[kk][tx * 4]);
            float av[4] = {af.x, af.y, af.z, af.w};
            float bv[4] = {bf.x, bf.y, bf.z, bf.w};
#pragma unroll
            for (int i = 0; i < 4; i++)
#pragma unroll
                for (int j = 0; j < 4; j++) acc[i][j] += av[i] * bv[j];
        }
        __syncthreads();
    }
#pragma unroll
    for (int i = 0; i < 4; i++) {
        int mg = m0 + ty * 4 + i;
        if (mg >= M) break;
#pragma unroll
        for (int j = 0; j < 4; j++) {
            int n = n0 + tx * 4 + j;
            float v = acc[i][j] + bias[n];
            if (EPI == 1) v += C[(size_t)mg * N + n];
            if (EPI == 2) v = gelu_f(v);
            C[(size_t)mg * N + n] = v;
        }
    }
}

// ---------------------------------------------------------------------------
// scores[b,h,i,j] = (q[b,i,h,:] . k[b,j,h,:]) / 8 ; batched over b*h
// ---------------------------------------------------------------------------
__global__ void scores_kernel(const float* __restrict__ q,
                              const float* __restrict__ k,
                              float* __restrict__ sc)
{
    __shared__ __align__(16) float As[16][68];
    __shared__ __align__(16) float Bs[16][68];
    int tx = threadIdx.x, ty = threadIdx.y;
    int t = ty * 16 + tx;
    int bh = blockIdx.z;
    int b = bh / NHH, h = bh % NHH;
    int n0 = blockIdx.x * 64;
    int m0 = blockIdx.y * 64;
    const float* qp = q + (size_t)(b * SS) * HH + h * 64;
    const float* kp = k + (size_t)(b * SS) * HH + h * 64;
    float acc[4][4] = {};

    for (int d0 = 0; d0 < 64; d0 += 16) {
#pragma unroll
        for (int r = 0; r < 4; r++) {
            int idx = t + r * 256;
            int m = idx >> 4, dd = idx & 15;
            int mg = m0 + m;
            As[dd][m] = (mg < SS) ? qp[(size_t)mg * HH + d0 + dd] : 0.0f;
            int ng = n0 + m;
            Bs[dd][m] = (ng < SS) ? kp[(size_t)ng * HH + d0 + dd] : 0.0f;
        }
        __syncthreads();
#pragma unroll
        for (int dd = 0; dd < 16; dd++) {
            float4 af = *(const float4*)(&As[dd][ty * 4]);
            float4 bf = *(const float4*)(&Bs[dd][tx * 4]);
            float av[4] = {af.x, af.y, af.z, af.w};
            float bv[4] = {bf.x, bf.y, bf.z, bf.w};
#pragma unroll
            for (int i = 0; i < 4; i++)
#pragma unroll
                for (int j = 0; j < 4; j++) acc[i][j] += av[i] * bv[j];
        }
        __syncthreads();
    }
    float* base = sc + (size_t)bh * SS * SS;
#pragma unroll
    for (int i = 0; i < 4; i++) {
        int ig = m0 + ty * 4 + i;
        if (ig >= SS) break;
#pragma unroll
        for (int j = 0; j < 4; j++) {
            int jg = n0 + tx * 4 + j;
            if (jg < SS) base[(size_t)ig * SS + jg] = acc[i][j] * 0.125f;
        }
    }
}

// ---------------------------------------------------------------------------
// Softmax over last dim (SS=1025). One 256-thread block per row.
// ---------------------------------------------------------------------------
__global__ void softmax_kernel(float* __restrict__ sc)
{
    size_t row = blockIdx.x;
    float* p = sc + row * SS;
    int t = threadIdx.x;
    __shared__ float sh[8];

    float vals[5];
    float m = -1e30f;
#pragma unroll
    for (int r = 0; r < 5; r++) {
        int idx = t + r * 256;
        vals[r] = (idx < SS) ? p[idx] : -1e30f;
        m = fmaxf(m, vals[r]);
    }
#pragma unroll
    for (int o = 16; o; o >>= 1) m = fmaxf(m, __shfl_xor_sync(0xffffffffu, m, o));
    if ((t & 31) == 0) sh[t >> 5] = m;
    __syncthreads();
    m = sh[0];
#pragma unroll
    for (int w = 1; w < 8; w++) m = fmaxf(m, sh[w]);
    __syncthreads();

    float s = 0.0f;
#pragma unroll
    for (int r = 0; r < 5; r++) {
        vals[r] = __expf(vals[r] - m);
        s += vals[r];
    }
#pragma unroll
    for (int o = 16; o; o >>= 1) s += __shfl_xor_sync(0xffffffffu, s, o);
    if ((t & 31) == 0) sh[t >> 5] = s;
    __syncthreads();
    s = sh[0] + sh[1] + sh[2] + sh[3] + sh[4] + sh[5] + sh[6] + sh[7];
    float inv = 1.0f / s;
#pragma unroll
    for (int r = 0; r < 5; r++) {
        int idx = t + r * 256;
        if (idx < SS) p[idx] = vals[r] * inv;
    }
}

// ---------------------------------------------------------------------------
// attn[b,i,h,:] = probs[b,h,i,:] @ v[b,:,h,:] ; M=S, N=64, K=S, batched b*h
// ---------------------------------------------------------------------------
__global__ void attnv_kernel(const float* __restrict__ pr,
                             const float* __restrict__ v,
                             float* __restrict__ out)
{
    __shared__ __align__(16) float As[16][68];
    __shared__ __align__(16) float Bs[16][64];
    int tx = threadIdx.x, ty = threadIdx.y;
    int t = ty * 16 + tx;
    int bh = blockIdx.z;
    int b = bh / NHH, h = bh % NHH;
    int m0 = blockIdx.y * 64;
    const float* pp = pr + (size_t)bh * SS * SS;
    const float* vp = v + (size_t)(b * SS) * HH + h * 64;
    float acc[4][4] = {};

    for (int k0 = 0; k0 < SS; k0 += 16) {
#pragma unroll
        for (int r = 0; r < 4; r++) {
            int idx = t + r * 256;
            int m = idx >> 4, kk = idx & 15;
            int mg = m0 + m, kg = k0 + kk;
            As[kk][m] = (mg < SS && kg < SS) ? pp[(size_t)mg * SS + kg] : 0.0f;
            int kb = idx >> 6, nb = idx & 63;
            int kg2 = k0 + kb;
            Bs[kb][nb] = (kg2 < SS) ? vp[(size_t)kg2 * HH + nb] : 0.0f;
        }
        __syncthreads();
#pragma unroll
        for (int kk = 0; kk < 16; kk++) {
            float4 af = *(const float4*)(&As[kk][ty * 4]);
            float4 bf = *(const float4*)(&Bs[kk][tx * 4]);
            float av[4] = {af.x, af.y, af.z, af.w};
            float bv[4] = {bf.x, bf.y, bf.z, bf.w};
#pragma unroll
            for (int i = 0; i < 4; i++)
#pragma unroll
                for (int j = 0; j < 4; j++) acc[i][j] += av[i] * bv[j];
        }
        __syncthreads();
    }
#pragma unroll
    for (int i = 0; i < 4; i++) {
        int mg = m0 + ty * 4 + i;
        if (mg >= SS) break;
#pragma unroll
        for (int j = 0; j < 4; j++) {
            int d = tx * 4 + j;
            out[(size_t)(b * SS + mg) * HH + h * 64 + d] = acc[i][j];
        }
    }
}

// ---------------------------------------------------------------------------
// Classifier: logits[b,n] = h[b,0,:] @ wc[:,n] + bc[n]
// ---------------------------------------------------------------------------
__global__ void classifier_kernel(const float* __restrict__ h,
                                  const float* __restrict__ wc,
                                  const float* __restrict__ bc,
                                  float* __restrict__ out)
{
    int t = blockIdx.x * 256 + threadIdx.x;
    if (t >= BB * NCC) return;
    int b = t / NCC, n = t % NCC;
    const float* hp = h + (size_t)(b * SS) * HH;
    float acc = 0.0f;
    for (int k = 0; k < HH; k++) acc += hp[k] * wc[(size_t)k * NCC + n];
    out[t] = acc + bc[n];
}

// ---------------------------------------------------------------------------
extern "C" void kernel_launch(void* const* d_in, const int* in_sizes, int n_in,
                              void* d_out, int out_size)
{
    const float* x    = (const float*)d_in[0];
    const float* cw   = (const float*)d_in[1];
    const float* cb   = (const float*)d_in[2];
    const float* cls  = (const float*)d_in[3];
    const float* pos  = (const float*)d_in[4];
    const float* ln1w = (const float*)d_in[5];
    const float* ln1b = (const float*)d_in[6];
    const float* wq   = (const float*)d_in[7];
    const float* bq   = (const float*)d_in[8];
    const float* wk   = (const float*)d_in[9];
    const float* bk   = (const float*)d_in[10];
    const float* wv   = (const float*)d_in[11];
    const float* bv   = (const float*)d_in[12];
    const float* wo   = (const float*)d_in[13];
    const float* bo   = (const float*)d_in[14];
    const float* ln2w = (const float*)d_in[15];
    const float* ln2b = (const float*)d_in[16];
    const float* w1   = (const float*)d_in[17];
    const float* b1   = (const float*)d_in[18];
    const float* w2   = (const float*)d_in[19];
    const float* b2   = (const float*)d_in[20];
    const float* wc   = (const float*)d_in[21];
    const float* bc   = (const float*)d_in[22];

    float *h, *hn, *q, *k, *v, *attn, *mlp, *sc;
    cudaGetSymbolAddress((void**)&h,    g_h);
    cudaGetSymbolAddress((void**)&hn,   g_hn);
    cudaGetSymbolAddress((void**)&q,    g_q);
    cudaGetSymbolAddress((void**)&k,    g_k);
    cudaGetSymbolAddress((void**)&v,    g_v);
    cudaGetSymbolAddress((void**)&attn, g_attn);
    cudaGetSymbolAddress((void**)&mlp,  g_mlp);
    cudaGetSymbolAddress((void**)&sc,   g_scores);

    dim3 blk(16, 16);

    // Patch embed + cls/pos
    patch_embed_kernel<<<dim3(HH / 64, MPATCH / 64), blk>>>(x, cw, cb, pos, h);
    cls_pos_kernel<<<(BB * HH + 255) / 256, 256>>>(cls, pos, h);

    dim3 gN384(HH / 64, (MTOK + 63) / 64);       // (6, 257)
    dim3 gN1536(II / 64, (MTOK + 63) / 64);      // (24, 257)
    dim3 gSc((SS + 63) / 64, (SS + 63) / 64, BB * NHH);  // (17,17,96)
    dim3 gAv(1, (SS + 63) / 64, BB * NHH);               // (1,17,96)

    for (int l = 0; l < LL; l++) {
        ln_kernel<<<MTOK, 128>>>(h, ln1w + l * HH, ln1b + l * HH, hn);
        gemm_kernel<0><<<gN384, blk>>>(hn, wq + (size_t)l * HH * HH, bq + l * HH, q, MTOK, HH, HH);
        gemm_kernel<0><<<gN384, blk>>>(hn, wk + (size_t)l * HH * HH, bk + l * HH, k, MTOK, HH, HH);
        gemm_kernel<0><<<gN384, blk>>>(hn, wv + (size_t)l * HH * HH, bv + l * HH, v, MTOK, HH, HH);
        scores_kernel<<<gSc, blk>>>(q, k, sc);
        softmax_kernel<<<BB * NHH * SS, 256>>>(sc);
        attnv_kernel<<<gAv, blk>>>(sc, v, attn);
        gemm_kernel<1><<<gN384, blk>>>(attn, wo + (size_t)l * HH * HH, bo + l * HH, h, MTOK, HH, HH);
        ln_kernel<<<MTOK, 128>>>(h, ln2w + l * HH, ln2b + l * HH, hn);
        gemm_kernel<2><<<gN1536, blk>>>(hn, w1 + (size_t)l * HH * II, b1 + l * II, mlp, MTOK, II, HH);
        gemm_kernel<1><<<gN384, blk>>>(mlp, w2 + (size_t)l * II * HH, b2 + l * HH, h, MTOK, HH, II);
    }

    classifier_kernel<<<(BB * NCC + 255) / 256, 256>>>(h, wc, bc, (float*)d_out);
}

// round 4
// speedup vs baseline: 2.7405x; 2.7405x over previous
#include <cuda_runtime.h>
#include <math.h>
#include <stdint.h>

#define BB 16
#define SS 1025
#define SP 1028            // padded scores row stride (16B-aligned rows)
#define HH 384
#define NHH 6
#define LL 12
#define II 1536
#define NCC 1000
#define MTOK (BB*SS)       // 16400
#define NPATCH 1024
#define MPATCH (BB*NPATCH) // 16384

// ---------------- scratch (__device__ globals; allocation-free rule) -------
__device__ __align__(256) float g_h[MTOK*HH];
__device__ __align__(256) float g_hn[MTOK*HH];
__device__ __align__(256) float g_q[MTOK*HH];
__device__ __align__(256) float g_k[MTOK*HH];
__device__ __align__(256) float g_v[MTOK*HH];
__device__ __align__(256) float g_attn[MTOK*HH];
__device__ __align__(256) float g_mlp[MTOK*II];
__device__ __align__(256) float g_scores[(size_t)BB*NHH*SS*SP];   // padded
// tf32-rounded weight copies
__device__ __align__(256) float g_wqt[LL*HH*HH];
__device__ __align__(256) float g_wkt[LL*HH*HH];
__device__ __align__(256) float g_wvt[LL*HH*HH];
__device__ __align__(256) float g_wot[LL*HH*HH];
__device__ __align__(256) float g_w1t[LL*HH*II];
__device__ __align__(256) float g_w2t[LL*II*HH];

// ---------------------------- helpers ---------------------------------------
__device__ __forceinline__ uint32_t smem_u32(const void* p) {
    uint32_t a;
    asm("{ .reg .u64 t; cvta.to.shared.u64 t, %1; cvt.u32.u64 %0, t; }"
        : "=r"(a) : "l"(p));
    return a;
}

__device__ __forceinline__ float to_tf32(float v) {
    uint32_t u;
    asm("cvt.rna.tf32.f32 %0, %1;" : "=r"(u) : "f"(v));
    return __uint_as_float(u);
}

__device__ __forceinline__ void cp16(uint32_t dst, const float* src, int nbytes) {
    asm volatile("cp.async.cg.shared.global [%0], [%1], 16, %2;"
                 :: "r"(dst), "l"(src), "r"(nbytes) : "memory");
}
#define CP_COMMIT asm volatile("cp.async.commit_group;" ::: "memory")
#define CP_WAIT0  asm volatile("cp.async.wait_group 0;" ::: "memory")

// D += A(16x8,row) * B(8x8,col), tf32
__device__ __forceinline__ void mma8(float* c, const uint32_t* a, const uint32_t* b) {
    asm volatile("mma.sync.aligned.m16n8k8.row.col.f32.tf32.tf32.f32 "
        "{%0,%1,%2,%3}, {%4,%5,%6,%7}, {%8,%9}, {%0,%1,%2,%3};"
        : "+f"(c[0]), "+f"(c[1]), "+f"(c[2]), "+f"(c[3])
        : "r"(a[0]), "r"(a[1]), "r"(a[2]), "r"(a[3]), "r"(b[0]), "r"(b[1]));
}

__device__ __forceinline__ float gelu_f(float u) {
    float a = -1.5957691216057308f * (u + 0.044715f * u * u * u);
    float e = __expf(fminf(a, 80.0f));
    float th = (1.0f - e) / (1.0f + e);
    return 0.5f * u * (1.0f + th);
}

// ------------------------- dense mma GEMM ------------------------------------
// C[M,N] = A[M,K] @ W[K,N] + bias. EPI 0: +tf32 round; 1: +residual; 2: gelu+round
// Block 128x128, 256 threads (8 warps, 4m x 2n), warp tile 32x64, K-chunk 32.
// smem: As[2][128][36] + Bs[2][32][136] = 71680 B
#define DG_SMEM ((2*128*36 + 2*32*136)*4)

template <int EPI>
__global__ void __launch_bounds__(256)
mma_gemm(const float* __restrict__ A, const float* __restrict__ Bw,
         const float* __restrict__ bias, float* __restrict__ C,
         int M, int N, int K)
{
    extern __shared__ __align__(16) float smbuf[];
    uint32_t sbase = smem_u32(smbuf);
    int tid = threadIdx.x, lane = tid & 31, w = tid >> 5;
    int gid = lane >> 2, tig = lane & 3;
    int wm0 = (w & 3) * 32, wn0 = (w >> 2) * 64;
    int m0 = blockIdx.y * 128, n0 = blockIdx.x * 128;

    float c[2][8][4];
#pragma unroll
    for (int i = 0; i < 2; i++)
#pragma unroll
        for (int j = 0; j < 8; j++)
#pragma unroll
            for (int e = 0; e < 4; e++) c[i][j][e] = 0.0f;

    int nch = K >> 5;
    auto load = [&](int ch, int s) {
        int k0 = ch * 32;
#pragma unroll
        for (int i = 0; i < 4; i++) {           // A: 128 rows x 8 f4
            int qd = tid + i * 256;
            int row = qd >> 3, c4 = qd & 7;
            uint32_t dst = sbase + (uint32_t)(s * 4608 + row * 36 + c4 * 4) * 4;
            cp16(dst, A + (size_t)(m0 + row) * K + k0 + c4 * 4,
                 (m0 + row < M) ? 16 : 0);
        }
#pragma unroll
        for (int i = 0; i < 4; i++) {           // B: 32 rows x 32 f4
            int qd = tid + i * 256;
            int row = qd >> 5, c4 = qd & 31;
            uint32_t dst = sbase + (uint32_t)(9216 + s * 4352 + row * 136 + c4 * 4) * 4;
            cp16(dst, Bw + (size_t)(k0 + row) * N + n0 + c4 * 4, 16);
        }
        CP_COMMIT;
    };

    load(0, 0);
    for (int ch = 0; ch < nch; ch++) {
        int s = ch & 1;
        CP_WAIT0;
        __syncthreads();
        if (ch + 1 < nch) load(ch + 1, s ^ 1);
        const float* As = smbuf + s * 4608;
        const float* Bs = smbuf + 9216 + s * 4352;
#pragma unroll
        for (int ks = 0; ks < 4; ks++) {
            int kk = ks * 8;
            uint32_t a[2][4], b[8][2];
#pragma unroll
            for (int mt = 0; mt < 2; mt++) {
                int r0 = wm0 + mt * 16 + gid;
                a[mt][0] = __float_as_uint(As[r0 * 36 + kk + tig]);
                a[mt][1] = __float_as_uint(As[(r0 + 8) * 36 + kk + tig]);
                a[mt][2] = __float_as_uint(As[r0 * 36 + kk + tig + 4]);
                a[mt][3] = __float_as_uint(As[(r0 + 8) * 36 + kk + tig + 4]);
            }
#pragma unroll
            for (int nt = 0; nt < 8; nt++) {
                int cn = wn0 + nt * 8 + gid;
                b[nt][0] = __float_as_uint(Bs[(kk + tig) * 136 + cn]);
                b[nt][1] = __float_as_uint(Bs[(kk + tig + 4) * 136 + cn]);
            }
#pragma unroll
            for (int mt = 0; mt < 2; mt++)
#pragma unroll
                for (int nt = 0; nt < 8; nt++)
                    mma8(c[mt][nt], a[mt], b[nt]);
        }
        __syncthreads();
    }

#pragma unroll
    for (int mt = 0; mt < 2; mt++) {
#pragma unroll
        for (int nt = 0; nt < 8; nt++) {
            int col = n0 + wn0 + nt * 8 + tig * 2;
            float b0 = bias[col], b1 = bias[col + 1];
#pragma unroll
            for (int h2 = 0; h2 < 2; h2++) {
                int row = m0 + wm0 + mt * 16 + gid + h2 * 8;
                if (row < M) {
                    float v0 = c[mt][nt][h2 * 2] + b0;
                    float v1 = c[mt][nt][h2 * 2 + 1] + b1;
                    float* cp_ = C + (size_t)row * N + col;
                    if (EPI == 1) { v0 += cp_[0]; v1 += cp_[1]; }
                    if (EPI == 2) { v0 = to_tf32(gelu_f(v0)); v1 = to_tf32(gelu_f(v1)); }
                    if (EPI == 0) { v0 = to_tf32(v0); v1 = to_tf32(v1); }
                    *(float2*)cp_ = make_float2(v0, v1);
                }
            }
        }
    }
}

// ------------------------- scores: Q @ K^T -----------------------------------
// scores[bh, i, j] = (q[i,:] . k[j,:]) / 8,  D=64; tiles 128x128.
// smem: Qs[128][68] + Ks[128][68] = 69632 B
#define SC_SMEM (2*128*68*4)

__global__ void __launch_bounds__(256)
mma_scores(const float* __restrict__ q, const float* __restrict__ k,
           float* __restrict__ sc)
{
    extern __shared__ __align__(16) float smbuf[];
    uint32_t sbase = smem_u32(smbuf);
    int tid = threadIdx.x, lane = tid & 31, w = tid >> 5;
    int gid = lane >> 2, tig = lane & 3;
    int wm0 = (w & 3) * 32, wn0 = (w >> 2) * 64;
    int bh = blockIdx.z, b = bh / NHH, h = bh % NHH;
    int m0 = blockIdx.y * 128, n0 = blockIdx.x * 128;
    const float* qp = q + (size_t)(b * SS) * HH + h * 64;
    const float* kp = k + (size_t)(b * SS) * HH + h * 64;

#pragma unroll
    for (int i = 0; i < 8; i++) {               // Q: 128 rows x 16 f4
        int qd = tid + i * 256;
        int row = qd >> 4, c4 = qd & 15;
        cp16(sbase + (uint32_t)(row * 68 + c4 * 4) * 4,
             qp + (size_t)(m0 + row) * HH + c4 * 4, (m0 + row < SS) ? 16 : 0);
    }
#pragma unroll
    for (int i = 0; i < 8; i++) {               // K: 128 rows x 16 f4
        int qd = tid + i * 256;
        int row = qd >> 4, c4 = qd & 15;
        cp16(sbase + (uint32_t)(8704 + row * 68 + c4 * 4) * 4,
             kp + (size_t)(n0 + row) * HH + c4 * 4, (n0 + row < SS) ? 16 : 0);
    }
    CP_COMMIT; CP_WAIT0;
    __syncthreads();

    float c[2][8][4];
#pragma unroll
    for (int i = 0; i < 2; i++)
#pragma unroll
        for (int j = 0; j < 8; j++)
#pragma unroll
            for (int e = 0; e < 4; e++) c[i][j][e] = 0.0f;

    const float* Qs = smbuf;
    const float* Ks = smbuf + 8704;
#pragma unroll
    for (int ks = 0; ks < 8; ks++) {
        int kk = ks * 8;
        uint32_t a[2][4], b2[8][2];
#pragma unroll
        for (int mt = 0; mt < 2; mt++) {
            int r0 = wm0 + mt * 16 + gid;
            a[mt][0] = __float_as_uint(Qs[r0 * 68 + kk + tig]);
            a[mt][1] = __float_as_uint(Qs[(r0 + 8) * 68 + kk + tig]);
            a[mt][2] = __float_as_uint(Qs[r0 * 68 + kk + tig + 4]);
            a[mt][3] = __float_as_uint(Qs[(r0 + 8) * 68 + kk + tig + 4]);
        }
#pragma unroll
        for (int nt = 0; nt < 8; nt++) {
            int cn = wn0 + nt * 8 + gid;
            b2[nt][0] = __float_as_uint(Ks[cn * 68 + kk + tig]);
            b2[nt][1] = __float_as_uint(Ks[cn * 68 + kk + tig + 4]);
        }
#pragma unroll
        for (int mt = 0; mt < 2; mt++)
#pragma unroll
            for (int nt = 0; nt < 8; nt++)
                mma8(c[mt][nt], a[mt], b2[nt]);
    }

    float* base = sc + (size_t)bh * SS * SP;
#pragma unroll
    for (int mt = 0; mt < 2; mt++) {
#pragma unroll
        for (int h2 = 0; h2 < 2; h2++) {
            int i = m0 + wm0 + mt * 16 + gid + h2 * 8;
            if (i >= SS) continue;
#pragma unroll
            for (int nt = 0; nt < 8; nt++) {
                int j = n0 + wn0 + nt * 8 + tig * 2;
                if (j < SS)     base[(size_t)i * SP + j]     = c[mt][nt][h2 * 2]     * 0.125f;
                if (j + 1 < SS) base[(size_t)i * SP + j + 1] = c[mt][nt][h2 * 2 + 1] * 0.125f;
            }
        }
    }
}

// ------------------------- attnv: P @ V --------------------------------------
// out[b, i, h*64+d] = sum_j P[bh,i,j] * v[b,j,h*64+d]. Tiles 128m x 64n, K-chunk 32.
// smem: Ps[2][128][36] + Vs[2][32][72] = 55296 B
#define AV_SMEM ((2*128*36 + 2*32*72)*4)

__global__ void __launch_bounds__(256)
mma_attnv(const float* __restrict__ pr, const float* __restrict__ v,
          float* __restrict__ out)
{
    extern __shared__ __align__(16) float smbuf[];
    uint32_t sbase = smem_u32(smbuf);
    int tid = threadIdx.x, lane = tid & 31, w = tid >> 5;
    int gid = lane >> 2, tig = lane & 3;
    int wm0 = (w & 3) * 32, wn0 = (w >> 2) * 32;
    int bh = blockIdx.y, b = bh / NHH, h = bh % NHH;
    int m0 = blockIdx.x * 128;
    const float* pp = pr + (size_t)bh * SS * SP;
    const float* vp = v + (size_t)(b * SS) * HH + h * 64;

    float c[2][4][4];
#pragma unroll
    for (int i = 0; i < 2; i++)
#pragma unroll
        for (int j = 0; j < 4; j++)
#pragma unroll
            for (int e = 0; e < 4; e++) c[i][j][e] = 0.0f;

    const int nch = (SS + 31) / 32;   // 33
    auto load = [&](int ch, int s) {
        int k0 = ch * 32;
#pragma unroll
        for (int i = 0; i < 4; i++) {           // P: 128 rows x 8 f4
            int qd = tid + i * 256;
            int row = qd >> 3, c4 = qd & 7;
            int kidx = k0 + c4 * 4;
            int nb = 0;
            if (m0 + row < SS) {
                int rem = (SS - kidx) * 4;
                nb = rem >= 16 ? 16 : (rem > 0 ? rem : 0);
            }
            uint32_t dst = sbase + (uint32_t)(s * 4608 + row * 36 + c4 * 4) * 4;
            cp16(dst, pp + (size_t)(m0 + row) * SP + kidx, nb);
        }
#pragma unroll
        for (int i = 0; i < 2; i++) {           // V: 32 rows x 16 f4
            int qd = tid + i * 256;
            int row = qd >> 4, c4 = qd & 15;
            uint32_t dst = sbase + (uint32_t)(9216 + s * 2304 + row * 72 + c4 * 4) * 4;
            cp16(dst, vp + (size_t)(k0 + row) * HH + c4 * 4, (k0 + row < SS) ? 16 : 0);
        }
        CP_COMMIT;
    };

    load(0, 0);
    for (int ch = 0; ch < nch; ch++) {
        int s = ch & 1;
        CP_WAIT0;
        __syncthreads();
        if (ch + 1 < nch) load(ch + 1, s ^ 1);
        const float* Ps = smbuf + s * 4608;
        const float* Vs = smbuf + 9216 + s * 2304;
#pragma unroll
        for (int ks = 0; ks < 4; ks++) {
            int kk = ks * 8;
            uint32_t a[2][4], b2[4][2];
#pragma unroll
            for (int mt = 0; mt < 2; mt++) {
                int r0 = wm0 + mt * 16 + gid;
                a[mt][0] = __float_as_uint(Ps[r0 * 36 + kk + tig]);
                a[mt][1] = __float_as_uint(Ps[(r0 + 8) * 36 + kk + tig]);
                a[mt][2] = __float_as_uint(Ps[r0 * 36 + kk + tig + 4]);
                a[mt][3] = __float_as_uint(Ps[(r0 + 8) * 36 + kk + tig + 4]);
            }
#pragma unroll
            for (int nt = 0; nt < 4; nt++) {
                int cn = wn0 + nt * 8 + gid;
                b2[nt][0] = __float_as_uint(Vs[(kk + tig) * 72 + cn]);
                b2[nt][1] = __float_as_uint(Vs[(kk + tig + 4) * 72 + cn]);
            }
#pragma unroll
            for (int mt = 0; mt < 2; mt++)
#pragma unroll
                for (int nt = 0; nt < 4; nt++)
                    mma8(c[mt][nt], a[mt], b2[nt]);
        }
        __syncthreads();
    }

#pragma unroll
    for (int mt = 0; mt < 2; mt++) {
#pragma unroll
        for (int h2 = 0; h2 < 2; h2++) {
            int i = m0 + wm0 + mt * 16 + gid + h2 * 8;
            if (i >= SS) continue;
            float* op = out + (size_t)(b * SS + i) * HH + h * 64;
#pragma unroll
            for (int nt = 0; nt < 4; nt++) {
                int d = wn0 + nt * 8 + tig * 2;
                *(float2*)(op + d) = make_float2(to_tf32(c[mt][nt][h2 * 2]),
                                                 to_tf32(c[mt][nt][h2 * 2 + 1]));
            }
        }
    }
}

// -------------------------- weight tf32 rounding ----------------------------
__global__ void round_tf32_kernel(const float* __restrict__ in,
                                  float* __restrict__ out, int n)
{
    int i = blockIdx.x * 256 + threadIdx.x;
    if (i < n) out[i] = to_tf32(in[i]);
}

// --------------------------- patch embed (SIMT) -----------------------------
__global__ void patch_embed_kernel(const float* __restrict__ x,
                                   const float* __restrict__ cw,
                                   const float* __restrict__ cb,
                                   const float* __restrict__ pos,
                                   float* __restrict__ h)
{
    __shared__ __align__(16) float As[16][68];
    __shared__ __align__(16) float Bs[16][68];
    int tx = threadIdx.x, ty = threadIdx.y;
    int t = ty * 16 + tx;
    int n0 = blockIdx.x * 64;
    int m0 = blockIdx.y * 64;
    float acc[4][4] = {};

    for (int k0 = 0; k0 < 768; k0 += 16) {
#pragma unroll
        for (int r = 0; r < 4; r++) {
            int idx = t + r * 256;
            int m = idx >> 4, kk = idx & 15;
            int k = k0 + kk;
            int mg = m0 + m;
            int b = mg >> 10, pi = mg & 1023;
            int i = pi >> 5, j = pi & 31;
            int c = k >> 8, rr = (k >> 4) & 15, qq = k & 15;
            As[kk][m] = x[((b * 3 + c) * 512 + i * 16 + rr) * 512 + j * 16 + qq];
            Bs[kk][m] = cw[(n0 + m) * 768 + k];
        }
        __syncthreads();
#pragma unroll
        for (int kk = 0; kk < 16; kk++) {
            float4 af = *(const float4*)(&As[kk][ty * 4]);
            float4 bf = *(const float4*)(&Bs[kk][tx * 4]);
            float av[4] = {af.x, af.y, af.z, af.w};
            float bv[4] = {bf.x, bf.y, bf.z, bf.w};
#pragma unroll
            for (int i = 0; i < 4; i++)
#pragma unroll
                for (int j = 0; j < 4; j++) acc[i][j] += av[i] * bv[j];
        }
        __syncthreads();
    }
#pragma unroll
    for (int i = 0; i < 4; i++) {
        int mg = m0 + ty * 4 + i;
        int b = mg >> 10, pi = mg & 1023;
        int row = b * SS + 1 + pi;
#pragma unroll
        for (int j = 0; j < 4; j++) {
            int o = n0 + tx * 4 + j;
            h[row * HH + o] = acc[i][j] + cb[o] + pos[(1 + pi) * HH + o];
        }
    }
}

__global__ void cls_pos_kernel(const float* __restrict__ cls,
                               const float* __restrict__ pos,
                               float* __restrict__ h)
{
    int t = blockIdx.x * 256 + threadIdx.x;
    if (t < BB * HH) {
        int b = t / HH, o = t % HH;
        h[(b * SS) * HH + o] = cls[o] + pos[o];
    }
}

// --------------------------- LayerNorm (tf32 out) ---------------------------
__global__ void ln_kernel(const float* __restrict__ in,
                          const float* __restrict__ w,
                          const float* __restrict__ b,
                          float* __restrict__ out)
{
    int row = blockIdx.x;
    const float* p = in + (size_t)row * HH;
    int t = threadIdx.x;            // 128 threads
    float v0 = p[t], v1 = p[t + 128], v2 = p[t + 256];

    __shared__ float sh[4];
    float s = v0 + v1 + v2;
#pragma unroll
    for (int o = 16; o; o >>= 1) s += __shfl_xor_sync(0xffffffffu, s, o);
    if ((t & 31) == 0) sh[t >> 5] = s;
    __syncthreads();
    float mu = (sh[0] + sh[1] + sh[2] + sh[3]) * (1.0f / 384.0f);
    __syncthreads();

    float d0 = v0 - mu, d1 = v1 - mu, d2 = v2 - mu;
    float sq = d0 * d0 + d1 * d1 + d2 * d2;
#pragma unroll
    for (int o = 16; o; o >>= 1) sq += __shfl_xor_sync(0xffffffffu, sq, o);
    if ((t & 31) == 0) sh[t >> 5] = sq;
    __syncthreads();
    float var = (sh[0] + sh[1] + sh[2] + sh[3]) * (1.0f / 384.0f);
    float inv = rsqrtf(var + 1e-5f);

    float* q = out + (size_t)row * HH;
    q[t]       = to_tf32(d0 * inv * w[t]       + b[t]);
    q[t + 128] = to_tf32(d1 * inv * w[t + 128] + b[t + 128]);
    q[t + 256] = to_tf32(d2 * inv * w[t + 256] + b[t + 256]);
}

// ------------------------------ softmax -------------------------------------
__global__ void softmax_kernel(float* __restrict__ sc)
{
    size_t row = blockIdx.x;           // bh*SS + i, rows are SP-strided
    float* p = sc + row * SP;
    int t = threadIdx.x;
    __shared__ float sh[8];

    float vals[5];
    float m = -1e30f;
#pragma unroll
    for (int r = 0; r < 5; r++) {
        int idx = t + r * 256;
        vals[r] = (idx < SS) ? p[idx] : -1e30f;
        m = fmaxf(m, vals[r]);
    }
#pragma unroll
    for (int o = 16; o; o >>= 1) m = fmaxf(m, __shfl_xor_sync(0xffffffffu, m, o));
    if ((t & 31) == 0) sh[t >> 5] = m;
    __syncthreads();
    m = sh[0];
#pragma unroll
    for (int w = 1; w < 8; w++) m = fmaxf(m, sh[w]);
    __syncthreads();

    float s = 0.0f;
#pragma unroll
    for (int r = 0; r < 5; r++) {
        vals[r] = __expf(vals[r] - m);
        s += vals[r];
    }
#pragma unroll
    for (int o = 16; o; o >>= 1) s += __shfl_xor_sync(0xffffffffu, s, o);
    if ((t & 31) == 0) sh[t >> 5] = s;
    __syncthreads();
    s = sh[0] + sh[1] + sh[2] + sh[3] + sh[4] + sh[5] + sh[6] + sh[7];
    float inv = 1.0f / s;
#pragma unroll
    for (int r = 0; r < 5; r++) {
        int idx = t + r * 256;
        if (idx < SS) p[idx] = to_tf32(vals[r] * inv);
    }
}

// ------------------------------- classifier ---------------------------------
__global__ void classifier_kernel(const float* __restrict__ h,
                                  const float* __restrict__ wc,
                                  const float* __restrict__ bc,
                                  float* __restrict__ out)
{
    int t = blockIdx.x * 256 + threadIdx.x;
    if (t >= BB * NCC) return;
    int b = t / NCC, n = t % NCC;
    const float* hp = h + (size_t)(b * SS) * HH;
    float acc = 0.0f;
    for (int k = 0; k < HH; k++) acc += hp[k] * wc[(size_t)k * NCC + n];
    out[t] = acc + bc[n];
}

// ------------------------------- host side ----------------------------------
extern "C" void kernel_launch(void* const* d_in, const int* in_sizes, int n_in,
                              void* d_out, int out_size)
{
    const float* x    = (const float*)d_in[0];
    const float* cw   = (const float*)d_in[1];
    const float* cb   = (const float*)d_in[2];
    const float* cls  = (const float*)d_in[3];
    const float* pos  = (const float*)d_in[4];
    const float* ln1w = (const float*)d_in[5];
    const float* ln1b = (const float*)d_in[6];
    const float* wq   = (const float*)d_in[7];
    const float* bq   = (const float*)d_in[8];
    const float* wk   = (const float*)d_in[9];
    const float* bk   = (const float*)d_in[10];
    const float* wv   = (const float*)d_in[11];
    const float* bv   = (const float*)d_in[12];
    const float* wo   = (const float*)d_in[13];
    const float* bo   = (const float*)d_in[14];
    const float* ln2w = (const float*)d_in[15];
    const float* ln2b = (const float*)d_in[16];
    const float* w1   = (const float*)d_in[17];
    const float* b1   = (const float*)d_in[18];
    const float* w2   = (const float*)d_in[19];
    const float* b2   = (const float*)d_in[20];
    const float* wc   = (const float*)d_in[21];
    const float* bc   = (const float*)d_in[22];

    float *h, *hn, *q, *k, *v, *attn, *mlp, *sc;
    float *wqt, *wkt, *wvt, *wot, *w1t, *w2t;
    cudaGetSymbolAddress((void**)&h,    g_h);
    cudaGetSymbolAddress((void**)&hn,   g_hn);
    cudaGetSymbolAddress((void**)&q,    g_q);
    cudaGetSymbolAddress((void**)&k,    g_k);
    cudaGetSymbolAddress((void**)&v,    g_v);
    cudaGetSymbolAddress((void**)&attn, g_attn);
    cudaGetSymbolAddress((void**)&mlp,  g_mlp);
    cudaGetSymbolAddress((void**)&sc,   g_scores);
    cudaGetSymbolAddress((void**)&wqt,  g_wqt);
    cudaGetSymbolAddress((void**)&wkt,  g_wkt);
    cudaGetSymbolAddress((void**)&wvt,  g_wvt);
    cudaGetSymbolAddress((void**)&wot,  g_wot);
    cudaGetSymbolAddress((void**)&w1t,  g_w1t);
    cudaGetSymbolAddress((void**)&w2t,  g_w2t);

    // tf32-round the GEMM weights
    {
        int nsq = LL * HH * HH, nmlp = LL * HH * II;
        round_tf32_kernel<<<(nsq + 255) / 256, 256>>>(wq, wqt, nsq);
        round_tf32_kernel<<<(nsq + 255) / 256, 256>>>(wk, wkt, nsq);
        round_tf32_kernel<<<(nsq + 255) / 256, 256>>>(wv, wvt, nsq);
        round_tf32_kernel<<<(nsq + 255) / 256, 256>>>(wo, wot, nsq);
        round_tf32_kernel<<<(nmlp + 255) / 256, 256>>>(w1, w1t, nmlp);
        round_tf32_kernel<<<(nmlp + 255) / 256, 256>>>(w2, w2t, nmlp);
    }

    cudaFuncSetAttribute(mma_gemm<0>, cudaFuncAttributeMaxDynamicSharedMemorySize, DG_SMEM);
    cudaFuncSetAttribute(mma_gemm<1>, cudaFuncAttributeMaxDynamicSharedMemorySize, DG_SMEM);
    cudaFuncSetAttribute(mma_gemm<2>, cudaFuncAttributeMaxDynamicSharedMemorySize, DG_SMEM);
    cudaFuncSetAttribute(mma_scores,  cudaFuncAttributeMaxDynamicSharedMemorySize, SC_SMEM);
    cudaFuncSetAttribute(mma_attnv,   cudaFuncAttributeMaxDynamicSharedMemorySize, AV_SMEM);

    dim3 blk(16, 16);
    patch_embed_kernel<<<dim3(HH / 64, MPATCH / 64), blk>>>(x, cw, cb, pos, h);
    cls_pos_kernel<<<(BB * HH + 255) / 256, 256>>>(cls, pos, h);

    int mt = (MTOK + 127) / 128;                 // 129
    dim3 g384(HH / 128, mt);                     // (3, 129)
    dim3 g1536(II / 128, mt);                    // (12, 129)
    int st = (SS + 127) / 128;                   // 9
    dim3 gSc(st, st, BB * NHH);                  // (9, 9, 96)
    dim3 gAv(st, BB * NHH);                      // (9, 96)

    for (int l = 0; l < LL; l++) {
        ln_kernel<<<MTOK, 128>>>(h, ln1w + l * HH, ln1b + l * HH, hn);
        mma_gemm<0><<<g384, 256, DG_SMEM>>>(hn, wqt + (size_t)l * HH * HH, bq + l * HH, q, MTOK, HH, HH);
        mma_gemm<0><<<g384, 256, DG_SMEM>>>(hn, wkt + (size_t)l * HH * HH, bk + l * HH, k, MTOK, HH, HH);
        mma_gemm<0><<<g384, 256, DG_SMEM>>>(hn, wvt + (size_t)l * HH * HH, bv + l * HH, v, MTOK, HH, HH);
        mma_scores<<<gSc, 256, SC_SMEM>>>(q, k, sc);
        softmax_kernel<<<BB * NHH * SS, 256>>>(sc);
        mma_attnv<<<gAv, 256, AV_SMEM>>>(sc, v, attn);
        mma_gemm<1><<<g384, 256, DG_SMEM>>>(attn, wot + (size_t)l * HH * HH, bo + l * HH, h, MTOK, HH, HH);
        ln_kernel<<<MTOK, 128>>>(h, ln2w + l * HH, ln2b + l * HH, hn);
        mma_gemm<2><<<g1536, 256, DG_SMEM>>>(hn, w1t + (size_t)l * HH * II, b1 + l * II, mlp, MTOK, II, HH);
        mma_gemm<1><<<g384, 256, DG_SMEM>>>(mlp, w2t + (size_t)l * II * HH, b2 + l * HH, h, MTOK, HH, II);
    }

    classifier_kernel<<<(BB * NCC + 255) / 256, 256>>>(h, wc, bc, (float*)d_out);
}

// round 5
// speedup vs baseline: 3.6449x; 1.3300x over previous
#include <cuda_runtime.h>
#include <math.h>
#include <stdint.h>

#define BB 16
#define SS 1025
#define HH 384
#define NHH 6
#define LL 12
#define II 1536
#define NCC 1000
#define MTOK (BB*SS)       // 16400
#define NPATCH 1024
#define MPATCH (BB*NPATCH) // 16384
#define QKVN 1152          // 3*HH

// ---------------- scratch (__device__ globals; allocation-free rule) -------
__device__ __align__(256) float g_h[MTOK*HH];
__device__ __align__(256) float g_hn[MTOK*HH];
__device__ __align__(256) float g_qkv[(size_t)MTOK*QKVN];
__device__ __align__(256) float g_attn[MTOK*HH];
__device__ __align__(256) float g_mlp[MTOK*II];
// tf32-rounded weights
__device__ __align__(256) float g_wqkv[(size_t)LL*HH*QKVN];   // packed [L][K=H][N=3H]
__device__ __align__(256) float g_bqkv[LL*QKVN];
__device__ __align__(256) float g_wot[LL*HH*HH];
__device__ __align__(256) float g_w1t[LL*HH*II];
__device__ __align__(256) float g_w2t[LL*II*HH];

// ---------------------------- helpers ---------------------------------------
__device__ __forceinline__ uint32_t smem_u32(const void* p) {
    uint32_t a;
    asm("{ .reg .u64 t; cvta.to.shared.u64 t, %1; cvt.u32.u64 %0, t; }"
        : "=r"(a) : "l"(p));
    return a;
}

__device__ __forceinline__ float to_tf32(float v) {
    uint32_t u;
    asm("cvt.rna.tf32.f32 %0, %1;" : "=r"(u) : "f"(v));
    return __uint_as_float(u);
}

__device__ __forceinline__ void cp16(uint32_t dst, const float* src, int nbytes) {
    asm volatile("cp.async.cg.shared.global [%0], [%1], 16, %2;"
                 :: "r"(dst), "l"(src), "r"(nbytes) : "memory");
}
#define CP_COMMIT asm volatile("cp.async.commit_group;" ::: "memory")
#define CP_WAIT0  asm volatile("cp.async.wait_group 0;" ::: "memory")
#define CP_WAIT1  asm volatile("cp.async.wait_group 1;" ::: "memory")

// D += A(16x8,row) * B(8x8,col), tf32
__device__ __forceinline__ void mma8(float* c, const uint32_t* a, const uint32_t* b) {
    asm volatile("mma.sync.aligned.m16n8k8.row.col.f32.tf32.tf32.f32 "
        "{%0,%1,%2,%3}, {%4,%5,%6,%7}, {%8,%9}, {%0,%1,%2,%3};"
        : "+f"(c[0]), "+f"(c[1]), "+f"(c[2]), "+f"(c[3])
        : "r"(a[0]), "r"(a[1]), "r"(a[2]), "r"(a[3]), "r"(b[0]), "r"(b[1]));
}

__device__ __forceinline__ float gelu_f(float u) {
    float a = -1.5957691216057308f * (u + 0.044715f * u * u * u);
    float e = __expf(fminf(a, 80.0f));
    float th = (1.0f - e) / (1.0f + e);
    return 0.5f * u * (1.0f + th);
}

// ------------------------- dense mma GEMM ------------------------------------
// C[M,N] = A[M,K] @ W[K,N] + bias. EPI 0: +tf32 round; 1: +residual; 2: gelu+round
// Block 128x128, 256 threads (8 warps, 4m x 2n), warp tile 32x64, K-chunk 32.
#define DG_SMEM ((2*128*36 + 2*32*136)*4)

template <int EPI>
__global__ void __launch_bounds__(256)
mma_gemm(const float* __restrict__ A, const float* __restrict__ Bw,
         const float* __restrict__ bias, float* __restrict__ C,
         int M, int N, int K)
{
    extern __shared__ __align__(16) float smbuf[];
    uint32_t sbase = smem_u32(smbuf);
    int tid = threadIdx.x, lane = tid & 31, w = tid >> 5;
    int gid = lane >> 2, tig = lane & 3;
    int wm0 = (w & 3) * 32, wn0 = (w >> 2) * 64;
    int m0 = blockIdx.y * 128, n0 = blockIdx.x * 128;

    float c[2][8][4];
#pragma unroll
    for (int i = 0; i < 2; i++)
#pragma unroll
        for (int j = 0; j < 8; j++)
#pragma unroll
            for (int e = 0; e < 4; e++) c[i][j][e] = 0.0f;

    int nch = K >> 5;
    auto load = [&](int ch, int s) {
        int k0 = ch * 32;
#pragma unroll
        for (int i = 0; i < 4; i++) {
            int qd = tid + i * 256;
            int row = qd >> 3, c4 = qd & 7;
            int mg = m0 + row < M ? m0 + row : M - 1;
            uint32_t dst = sbase + (uint32_t)(s * 4608 + row * 36 + c4 * 4) * 4;
            cp16(dst, A + (size_t)mg * K + k0 + c4 * 4, (m0 + row < M) ? 16 : 0);
        }
#pragma unroll
        for (int i = 0; i < 4; i++) {
            int qd = tid + i * 256;
            int row = qd >> 5, c4 = qd & 31;
            uint32_t dst = sbase + (uint32_t)(9216 + s * 4352 + row * 136 + c4 * 4) * 4;
            cp16(dst, Bw + (size_t)(k0 + row) * N + n0 + c4 * 4, 16);
        }
        CP_COMMIT;
    };

    load(0, 0);
    for (int ch = 0; ch < nch; ch++) {
        int s = ch & 1;
        CP_WAIT0;
        __syncthreads();
        if (ch + 1 < nch) load(ch + 1, s ^ 1);
        const float* As = smbuf + s * 4608;
        const float* Bs = smbuf + 9216 + s * 4352;
#pragma unroll
        for (int ks = 0; ks < 4; ks++) {
            int kk = ks * 8;
            uint32_t a[2][4], b[8][2];
#pragma unroll
            for (int mt = 0; mt < 2; mt++) {
                int r0 = wm0 + mt * 16 + gid;
                a[mt][0] = __float_as_uint(As[r0 * 36 + kk + tig]);
                a[mt][1] = __float_as_uint(As[(r0 + 8) * 36 + kk + tig]);
                a[mt][2] = __float_as_uint(As[r0 * 36 + kk + tig + 4]);
                a[mt][3] = __float_as_uint(As[(r0 + 8) * 36 + kk + tig + 4]);
            }
#pragma unroll
            for (int nt = 0; nt < 8; nt++) {
                int cn = wn0 + nt * 8 + gid;
                b[nt][0] = __float_as_uint(Bs[(kk + tig) * 136 + cn]);
                b[nt][1] = __float_as_uint(Bs[(kk + tig + 4) * 136 + cn]);
            }
#pragma unroll
            for (int mt = 0; mt < 2; mt++)
#pragma unroll
                for (int nt = 0; nt < 8; nt++)
                    mma8(c[mt][nt], a[mt], b[nt]);
        }
        __syncthreads();
    }

#pragma unroll
    for (int mt = 0; mt < 2; mt++) {
#pragma unroll
        for (int nt = 0; nt < 8; nt++) {
            int col = n0 + wn0 + nt * 8 + tig * 2;
            float b0 = bias[col], b1 = bias[col + 1];
#pragma unroll
            for (int h2 = 0; h2 < 2; h2++) {
                int row = m0 + wm0 + mt * 16 + gid + h2 * 8;
                if (row < M) {
                    float v0 = c[mt][nt][h2 * 2] + b0;
                    float v1 = c[mt][nt][h2 * 2 + 1] + b1;
                    float* cp_ = C + (size_t)row * N + col;
                    if (EPI == 1) { v0 += cp_[0]; v1 += cp_[1]; }
                    if (EPI == 2) { v0 = to_tf32(gelu_f(v0)); v1 = to_tf32(gelu_f(v1)); }
                    if (EPI == 0) { v0 = to_tf32(v0); v1 = to_tf32(v1); }
                    *(float2*)cp_ = make_float2(v0, v1);
                }
            }
        }
    }
}

// ------------------------- flash attention -----------------------------------
// Per block: one (bh, 128-row q tile). K/V chunks of 128 keys, double-buffered.
// 8 warps, warp tile 16 rows x full 128-col score width.
// smem: Ks[2][128][68] + Vs[2][128][72]
#define FA_KS 8704            // floats per K stage
#define FA_VS 9216            // floats per V stage
#define FA_VBASE (2*FA_KS)    // 17408
#define FA_SMEM ((2*FA_KS + 2*FA_VS)*4)   // 143360 B
#define NCHK 9                // ceil(1025/128)

__global__ void __launch_bounds__(256)
flash_attn(const float* __restrict__ qkv, float* __restrict__ out)
{
    extern __shared__ __align__(16) float smbuf[];
    uint32_t sbase = smem_u32(smbuf);
    int tid = threadIdx.x, lane = tid & 31, w = tid >> 5;
    int gid = lane >> 2, tig = lane & 3;
    int bh = blockIdx.y, b = bh / NHH, h = bh % NHH;
    int m0 = blockIdx.x * 128;
    int wm0 = w * 16;
    const size_t rowstr = QKVN;
    const float* qbase = qkv + (size_t)(b * SS) * rowstr + h * 64;

    // ---- Q fragments (scaled by 1/8) ----
    float qa[8][4];
    {
        int r0 = m0 + wm0 + gid, r1 = r0 + 8;
        const float* q0 = qbase + (size_t)(r0 < SS ? r0 : 0) * rowstr;
        const float* q1 = qbase + (size_t)(r1 < SS ? r1 : 0) * rowstr;
        float z0 = (r0 < SS) ? 0.125f : 0.0f;
        float z1 = (r1 < SS) ? 0.125f : 0.0f;
#pragma unroll
        for (int ks = 0; ks < 8; ks++) {
            qa[ks][0] = q0[ks * 8 + tig] * z0;
            qa[ks][1] = q1[ks * 8 + tig] * z1;
            qa[ks][2] = q0[ks * 8 + tig + 4] * z0;
            qa[ks][3] = q1[ks * 8 + tig + 4] * z1;
        }
    }

    float o[8][4];
#pragma unroll
    for (int i = 0; i < 8; i++)
#pragma unroll
        for (int e = 0; e < 4; e++) o[i][e] = 0.0f;
    float m_run[2] = {-1e30f, -1e30f};
    float l_run[2] = {0.0f, 0.0f};

    auto loadKV = [&](int c, int s) {
        int jb = c * 128;
#pragma unroll
        for (int i = 0; i < 8; i++) {        // K chunk: 128 x 64
            int qd = tid + i * 256;
            int row = qd >> 4, c4 = qd & 15;
            int j = jb + row;
            const float* src = qkv + (size_t)(b * SS + (j < SS ? j : 0)) * rowstr
                             + 384 + h * 64 + c4 * 4;
            cp16(sbase + (uint32_t)(s * FA_KS + row * 68 + c4 * 4) * 4, src,
                 (j < SS) ? 16 : 0);
        }
#pragma unroll
        for (int i = 0; i < 8; i++) {        // V chunk: 128 x 64
            int qd = tid + i * 256;
            int row = qd >> 4, c4 = qd & 15;
            int j = jb + row;
            const float* src = qkv + (size_t)(b * SS + (j < SS ? j : 0)) * rowstr
                             + 768 + h * 64 + c4 * 4;
            cp16(sbase + (uint32_t)(FA_VBASE + s * FA_VS + row * 72 + c4 * 4) * 4, src,
                 (j < SS) ? 16 : 0);
        }
        CP_COMMIT;
    };

    loadKV(0, 0);
    loadKV(1, 1);

    for (int c = 0; c < NCHK; c++) {
        int s = c & 1;
        if (c == NCHK - 1) { CP_WAIT0; } else { CP_WAIT1; }
        __syncthreads();
        const float* Ksm = smbuf + s * FA_KS;
        const float* Vsm = smbuf + FA_VBASE + s * FA_VS;

        // ---- scores: QK^T, 16 rows x 128 cols per warp ----
        float sc[16][4];
#pragma unroll
        for (int i = 0; i < 16; i++)
#pragma unroll
            for (int e = 0; e < 4; e++) sc[i][e] = 0.0f;
#pragma unroll
        for (int ks = 0; ks < 8; ks++) {
            int kk = ks * 8;
#pragma unroll
            for (int nt = 0; nt < 16; nt++) {
                int jn = nt * 8 + gid;
                uint32_t bb[2] = { __float_as_uint(Ksm[jn * 68 + kk + tig]),
                                   __float_as_uint(Ksm[jn * 68 + kk + tig + 4]) };
                mma8(sc[nt], (const uint32_t*)qa[ks], bb);
            }
        }

        // ---- mask invalid columns ----
        int jb = c * 128;
        if (jb + 128 > SS) {
#pragma unroll
            for (int nt = 0; nt < 16; nt++) {
                int j0 = jb + nt * 8 + tig * 2;
                if (j0 >= SS)     { sc[nt][0] = -1e30f; sc[nt][2] = -1e30f; }
                if (j0 + 1 >= SS) { sc[nt][1] = -1e30f; sc[nt][3] = -1e30f; }
            }
        }

        // ---- online softmax ----
#pragma unroll
        for (int h2 = 0; h2 < 2; h2++) {
            float mx = -1e30f;
#pragma unroll
            for (int nt = 0; nt < 16; nt++)
                mx = fmaxf(mx, fmaxf(sc[nt][h2 * 2], sc[nt][h2 * 2 + 1]));
            mx = fmaxf(mx, __shfl_xor_sync(0xffffffffu, mx, 1));
            mx = fmaxf(mx, __shfl_xor_sync(0xffffffffu, mx, 2));
            float mnew = fmaxf(m_run[h2], mx);
            float corr = __expf(m_run[h2] - mnew);
            m_run[h2] = mnew;
            float rs = 0.0f;
#pragma unroll
            for (int nt = 0; nt < 16; nt++) {
                float p0 = __expf(sc[nt][h2 * 2] - mnew);
                float p1 = __expf(sc[nt][h2 * 2 + 1] - mnew);
                sc[nt][h2 * 2] = p0; sc[nt][h2 * 2 + 1] = p1;
                rs += p0 + p1;
            }
            rs += __shfl_xor_sync(0xffffffffu, rs, 1);
            rs += __shfl_xor_sync(0xffffffffu, rs, 2);
            l_run[h2] = l_run[h2] * corr + rs;
#pragma unroll
            for (int ng = 0; ng < 8; ng++) {
                o[ng][h2 * 2] *= corr;
                o[ng][h2 * 2 + 1] *= corr;
            }
        }

        // ---- PV: P(16x128) @ V(128x64) ----
        int srcA = (lane & ~3) | (tig >> 1);
        int srcB = srcA + 2;
#pragma unroll
        for (int ks = 0; ks < 16; ks++) {
            float r0 = __shfl_sync(0xffffffffu, sc[ks][0], srcA);
            float r1 = __shfl_sync(0xffffffffu, sc[ks][1], srcA);
            float r2 = __shfl_sync(0xffffffffu, sc[ks][2], srcA);
            float r3 = __shfl_sync(0xffffffffu, sc[ks][3], srcA);
            float s0 = __shfl_sync(0xffffffffu, sc[ks][0], srcB);
            float s1 = __shfl_sync(0xffffffffu, sc[ks][1], srcB);
            float s2 = __shfl_sync(0xffffffffu, sc[ks][2], srcB);
            float s3 = __shfl_sync(0xffffffffu, sc[ks][3], srcB);
            uint32_t pa[4];
            pa[0] = __float_as_uint((tig & 1) ? r1 : r0);
            pa[1] = __float_as_uint((tig & 1) ? r3 : r2);
            pa[2] = __float_as_uint((tig & 1) ? s1 : s0);
            pa[3] = __float_as_uint((tig & 1) ? s3 : s2);
            int kk = ks * 8;
#pragma unroll
            for (int ng = 0; ng < 8; ng++) {
                int cn = ng * 8 + gid;
                uint32_t bb[2] = { __float_as_uint(Vsm[(kk + tig) * 72 + cn]),
                                   __float_as_uint(Vsm[(kk + tig + 4) * 72 + cn]) };
                mma8(o[ng], pa, bb);
            }
        }

        __syncthreads();
        if (c + 2 < NCHK) loadKV(c + 2, s);
    }

    // ---- epilogue ----
#pragma unroll
    for (int h2 = 0; h2 < 2; h2++) {
        int i = m0 + wm0 + gid + h2 * 8;
        if (i >= SS) continue;
        float invl = 1.0f / l_run[h2];
        float* op = out + (size_t)(b * SS + i) * HH + h * 64;
#pragma unroll
        for (int ng = 0; ng < 8; ng++) {
            int d = ng * 8 + tig * 2;
            op[d]     = to_tf32(o[ng][h2 * 2] * invl);
            op[d + 1] = to_tf32(o[ng][h2 * 2 + 1] * invl);
        }
    }
}

// -------------------------- weight prep -------------------------------------
__global__ void round_tf32_kernel(const float* __restrict__ in,
                                  float* __restrict__ out, int n)
{
    int i = blockIdx.x * 256 + threadIdx.x;
    if (i < n) out[i] = to_tf32(in[i]);
}

__global__ void pack_qkv_w(const float* __restrict__ wq,
                           const float* __restrict__ wk,
                           const float* __restrict__ wv,
                           float* __restrict__ out)
{
    int idx = blockIdx.x * 256 + threadIdx.x;
    if (idx >= LL * HH * QKVN) return;
    int n = idx % QKVN;
    int r = (idx / QKVN) % HH;
    int l = idx / (QKVN * HH);
    const float* src = (n < HH) ? wq : (n < 2 * HH) ? wk : wv;
    int nn = n % HH;
    out[idx] = to_tf32(src[((size_t)l * HH + r) * HH + nn]);
}

__global__ void pack_qkv_b(const float* __restrict__ bq,
                           const float* __restrict__ bk,
                           const float* __restrict__ bv,
                           float* __restrict__ out)
{
    int idx = blockIdx.x * 256 + threadIdx.x;
    if (idx >= LL * QKVN) return;
    int n = idx % QKVN;
    int l = idx / QKVN;
    const float* src = (n < HH) ? bq : (n < 2 * HH) ? bk : bv;
    out[idx] = src[l * HH + n % HH];
}

// --------------------------- patch embed (SIMT) -----------------------------
__global__ void patch_embed_kernel(const float* __restrict__ x,
                                   const float* __restrict__ cw,
                                   const float* __restrict__ cb,
                                   const float* __restrict__ pos,
                                   float* __restrict__ h)
{
    __shared__ __align__(16) float As[16][68];
    __shared__ __align__(16) float Bs[16][68];
    int tx = threadIdx.x, ty = threadIdx.y;
    int t = ty * 16 + tx;
    int n0 = blockIdx.x * 64;
    int m0 = blockIdx.y * 64;
    float acc[4][4] = {};

    for (int k0 = 0; k0 < 768; k0 += 16) {
#pragma unroll
        for (int r = 0; r < 4; r++) {
            int idx = t + r * 256;
            int m = idx >> 4, kk = idx & 15;
            int k = k0 + kk;
            int mg = m0 + m;
            int b = mg >> 10, pi = mg & 1023;
            int i = pi >> 5, j = pi & 31;
            int c = k >> 8, rr = (k >> 4) & 15, qq = k & 15;
            As[kk][m] = x[((b * 3 + c) * 512 + i * 16 + rr) * 512 + j * 16 + qq];
            Bs[kk][m] = cw[(n0 + m) * 768 + k];
        }
        __syncthreads();
#pragma unroll
        for (int kk = 0; kk < 16; kk++) {
            float4 af = *(const float4*)(&As[kk][ty * 4]);
            float4 bf = *(const float4*)(&Bs[kk][tx * 4]);
            float av[4] = {af.x, af.y, af.z, af.w};
            float bv[4] = {bf.x, bf.y, bf.z, bf.w};
#pragma unroll
            for (int i = 0; i < 4; i++)
#pragma unroll
                for (int j = 0; j < 4; j++) acc[i][j] += av[i] * bv[j];
        }
        __syncthreads();
    }
#pragma unroll
    for (int i = 0; i < 4; i++) {
        int mg = m0 + ty * 4 + i;
        int b = mg >> 10, pi = mg & 1023;
        int row = b * SS + 1 + pi;
#pragma unroll
        for (int j = 0; j < 4; j++) {
            int o = n0 + tx * 4 + j;
            h[row * HH + o] = acc[i][j] + cb[o] + pos[(1 + pi) * HH + o];
        }
    }
}

__global__ void cls_pos_kernel(const float* __restrict__ cls,
                               const float* __restrict__ pos,
                               float* __restrict__ h)
{
    int t = blockIdx.x * 256 + threadIdx.x;
    if (t < BB * HH) {
        int b = t / HH, o = t % HH;
        h[(b * SS) * HH + o] = cls[o] + pos[o];
    }
}

// --------------------------- LayerNorm (tf32 out) ---------------------------
__global__ void ln_kernel(const float* __restrict__ in,
                          const float* __restrict__ w,
                          const float* __restrict__ b,
                          float* __restrict__ out)
{
    int row = blockIdx.x;
    const float* p = in + (size_t)row * HH;
    int t = threadIdx.x;            // 128 threads
    float v0 = p[t], v1 = p[t + 128], v2 = p[t + 256];

    __shared__ float sh[4];
    float s = v0 + v1 + v2;
#pragma unroll
    for (int o = 16; o; o >>= 1) s += __shfl_xor_sync(0xffffffffu, s, o);
    if ((t & 31) == 0) sh[t >> 5] = s;
    __syncthreads();
    float mu = (sh[0] + sh[1] + sh[2] + sh[3]) * (1.0f / 384.0f);
    __syncthreads();

    float d0 = v0 - mu, d1 = v1 - mu, d2 = v2 - mu;
    float sq = d0 * d0 + d1 * d1 + d2 * d2;
#pragma unroll
    for (int o = 16; o; o >>= 1) sq += __shfl_xor_sync(0xffffffffu, sq, o);
    if ((t & 31) == 0) sh[t >> 5] = sq;
    __syncthreads();
    float var = (sh[0] + sh[1] + sh[2] + sh[3]) * (1.0f / 384.0f);
    float inv = rsqrtf(var + 1e-5f);

    float* q = out + (size_t)row * HH;
    q[t]       = to_tf32(d0 * inv * w[t]       + b[t]);
    q[t + 128] = to_tf32(d1 * inv * w[t + 128] + b[t + 128]);
    q[t + 256] = to_tf32(d2 * inv * w[t + 256] + b[t + 256]);
}

// ------------------------------- classifier ---------------------------------
__global__ void classifier_kernel(const float* __restrict__ h,
                                  const float* __restrict__ wc,
                                  const float* __restrict__ bc,
                                  float* __restrict__ out)
{
    int t = blockIdx.x * 256 + threadIdx.x;
    if (t >= BB * NCC) return;
    int b = t / NCC, n = t % NCC;
    const float* hp = h + (size_t)(b * SS) * HH;
    float acc = 0.0f;
    for (int k = 0; k < HH; k++) acc += hp[k] * wc[(size_t)k * NCC + n];
    out[t] = acc + bc[n];
}

// ------------------------------- host side ----------------------------------
extern "C" void kernel_launch(void* const* d_in, const int* in_sizes, int n_in,
                              void* d_out, int out_size)
{
    const float* x    = (const float*)d_in[0];
    const float* cw   = (const float*)d_in[1];
    const float* cb   = (const float*)d_in[2];
    const float* cls  = (const float*)d_in[3];
    const float* pos  = (const float*)d_in[4];
    const float* ln1w = (const float*)d_in[5];
    const float* ln1b = (const float*)d_in[6];
    const float* wq   = (const float*)d_in[7];
    const float* bq   = (const float*)d_in[8];
    const float* wk   = (const float*)d_in[9];
    const float* bk   = (const float*)d_in[10];
    const float* wv   = (const float*)d_in[11];
    const float* bv   = (const float*)d_in[12];
    const float* wo   = (const float*)d_in[13];
    const float* bo   = (const float*)d_in[14];
    const float* ln2w = (const float*)d_in[15];
    const float* ln2b = (const float*)d_in[16];
    const float* w1   = (const float*)d_in[17];
    const float* b1   = (const float*)d_in[18];
    const float* w2   = (const float*)d_in[19];
    const float* b2   = (const float*)d_in[20];
    const float* wc   = (const float*)d_in[21];
    const float* bc   = (const float*)d_in[22];

    float *h, *hn, *qkv, *attn, *mlp;
    float *wqkv, *bqkv, *wot, *w1t, *w2t;
    cudaGetSymbolAddress((void**)&h,    g_h);
    cudaGetSymbolAddress((void**)&hn,   g_hn);
    cudaGetSymbolAddress((void**)&qkv,  g_qkv);
    cudaGetSymbolAddress((void**)&attn, g_attn);
    cudaGetSymbolAddress((void**)&mlp,  g_mlp);
    cudaGetSymbolAddress((void**)&wqkv, g_wqkv);
    cudaGetSymbolAddress((void**)&bqkv, g_bqkv);
    cudaGetSymbolAddress((void**)&wot,  g_wot);
    cudaGetSymbolAddress((void**)&w1t,  g_w1t);
    cudaGetSymbolAddress((void**)&w2t,  g_w2t);

    // weight prep
    {
        int nqkv = LL * HH * QKVN, nb = LL * QKVN;
        int nsq = LL * HH * HH, nmlp = LL * HH * II;
        pack_qkv_w<<<(nqkv + 255) / 256, 256>>>(wq, wk, wv, wqkv);
        pack_qkv_b<<<(nb + 255) / 256, 256>>>(bq, bk, bv, bqkv);
        round_tf32_kernel<<<(nsq + 255) / 256, 256>>>(wo, wot, nsq);
        round_tf32_kernel<<<(nmlp + 255) / 256, 256>>>(w1, w1t, nmlp);
        round_tf32_kernel<<<(nmlp + 255) / 256, 256>>>(w2, w2t, nmlp);
    }

    cudaFuncSetAttribute(mma_gemm<0>, cudaFuncAttributeMaxDynamicSharedMemorySize, DG_SMEM);
    cudaFuncSetAttribute(mma_gemm<1>, cudaFuncAttributeMaxDynamicSharedMemorySize, DG_SMEM);
    cudaFuncSetAttribute(mma_gemm<2>, cudaFuncAttributeMaxDynamicSharedMemorySize, DG_SMEM);
    cudaFuncSetAttribute(flash_attn,  cudaFuncAttributeMaxDynamicSharedMemorySize, FA_SMEM);

    dim3 blk(16, 16);
    patch_embed_kernel<<<dim3(HH / 64, MPATCH / 64), blk>>>(x, cw, cb, pos, h);
    cls_pos_kernel<<<(BB * HH + 255) / 256, 256>>>(cls, pos, h);

    int mt = (MTOK + 127) / 128;                 // 129
    dim3 gQKV(QKVN / 128, mt);                   // (9, 129)
    dim3 g384(HH / 128, mt);                     // (3, 129)
    dim3 g1536(II / 128, mt);                    // (12, 129)
    dim3 gFA((SS + 127) / 128, BB * NHH);        // (9, 96)

    for (int l = 0; l < LL; l++) {
        ln_kernel<<<MTOK, 128>>>(h, ln1w + l * HH, ln1b + l * HH, hn);
        mma_gemm<0><<<gQKV, 256, DG_SMEM>>>(hn, wqkv + (size_t)l * HH * QKVN,
                                            bqkv + l * QKVN, qkv, MTOK, QKVN, HH);
        flash_attn<<<gFA, 256, FA_SMEM>>>(qkv, attn);
        mma_gemm<1><<<g384, 256, DG_SMEM>>>(attn, wot + (size_t)l * HH * HH,
                                            bo + l * HH, h, MTOK, HH, HH);
        ln_kernel<<<MTOK, 128>>>(h, ln2w + l * HH, ln2b + l * HH, hn);
        mma_gemm<2><<<g1536, 256, DG_SMEM>>>(hn, w1t + (size_t)l * HH * II,
                                             b1 + l * II, mlp, MTOK, II, HH);
        mma_gemm<1><<<g384, 256, DG_SMEM>>>(mlp, w2t + (size_t)l * II * HH,
                                            b2 + l * HH, h, MTOK, HH, II);
    }

    classifier_kernel<<<(BB * NCC + 255) / 256, 256>>>(h, wc, bc, (float*)d_out);
}

// round 6
// speedup vs baseline: 6.2053x; 1.7024x over previous
#include <cuda_runtime.h>
#include <cuda_fp16.h>
#include <math.h>
#include <stdint.h>

#define BB 16
#define SS 1025
#define HH 384
#define NHH 6
#define LL 12
#define II 1536
#define NCC 1000
#define MTOK (BB*SS)       // 16400
#define NPATCH 1024
#define MPATCH (BB*NPATCH) // 16384
#define QKVN 1152          // 3*HH

// ---------------- scratch (__device__ globals; allocation-free rule) -------
__device__ __align__(256) float  g_h[MTOK*HH];
__device__ __align__(256) __half g_hn[MTOK*HH];
__device__ __align__(256) __half g_qkv[(size_t)MTOK*QKVN];
__device__ __align__(256) __half g_attn[MTOK*HH];
__device__ __align__(256) __half g_mlp[MTOK*II];
// fp16 weights, pre-transposed to [L][N][K]
__device__ __align__(256) __half g_wqkv[(size_t)LL*QKVN*HH];
__device__ __align__(256) float  g_bqkv[LL*QKVN];
__device__ __align__(256) __half g_wot[LL*HH*HH];
__device__ __align__(256) __half g_w1t[(size_t)LL*II*HH];
__device__ __align__(256) __half g_w2t[(size_t)LL*HH*II];

// ---------------------------- helpers ---------------------------------------
__device__ __forceinline__ uint32_t smem_u32(const void* p) {
    uint32_t a;
    asm("{ .reg .u64 t; cvta.to.shared.u64 t, %1; cvt.u32.u64 %0, t; }"
        : "=r"(a) : "l"(p));
    return a;
}

__device__ __forceinline__ void cp16(uint32_t dst, const void* src, int nbytes) {
    asm volatile("cp.async.cg.shared.global [%0], [%1], 16, %2;"
                 :: "r"(dst), "l"(src), "r"(nbytes) : "memory");
}
#define CP_COMMIT asm volatile("cp.async.commit_group;" ::: "memory")
#define CP_WAIT0  asm volatile("cp.async.wait_group 0;" ::: "memory")
#define CP_WAIT1  asm volatile("cp.async.wait_group 1;" ::: "memory")

// D += A(16x16,row,f16) * B(16x8,col,f16), f32 accum
__device__ __forceinline__ void mma16(float* c, const uint32_t* a,
                                      uint32_t b0, uint32_t b1) {
    asm volatile("mma.sync.aligned.m16n8k16.row.col.f32.f16.f16.f32 "
        "{%0,%1,%2,%3}, {%4,%5,%6,%7}, {%8,%9}, {%0,%1,%2,%3};"
        : "+f"(c[0]), "+f"(c[1]), "+f"(c[2]), "+f"(c[3])
        : "r"(a[0]), "r"(a[1]), "r"(a[2]), "r"(a[3]), "r"(b0), "r"(b1));
}

__device__ __forceinline__ void ldmx4t(uint32_t& r0, uint32_t& r1,
                                       uint32_t& r2, uint32_t& r3, uint32_t addr) {
    asm volatile("ldmatrix.sync.aligned.m8n8.x4.trans.shared.b16 {%0,%1,%2,%3}, [%4];"
        : "=r"(r0), "=r"(r1), "=r"(r2), "=r"(r3) : "r"(addr));
}

__device__ __forceinline__ float gelu_f(float u) {
    float a = -1.5957691216057308f * (u + 0.044715f * u * u * u);
    float e = __expf(fminf(a, 80.0f));
    float th = (1.0f - e) / (1.0f + e);
    return 0.5f * u * (1.0f + th);
}

// ------------------------- dense mma GEMM (fp16) -----------------------------
// C[M,N] = A[M,K] @ W^T (W stored [N][K]) + bias.
// EPI 0: ->fp16; 1: +residual ->fp32; 2: gelu ->fp16
// Block 128x128, 256 thr (8 warps, 4m x 2n), warp 32x64, K-chunk 64, 2 stages.
// smem halves: A[2][128*72], B[2][128*72] = 73728 B
#define DG_SMEM (4*128*72*2)

template <int EPI, typename Tout>
__global__ void __launch_bounds__(256)
mma_gemm(const __half* __restrict__ A, const __half* __restrict__ Bw,
         const float* __restrict__ bias, Tout* __restrict__ C,
         int M, int N, int K)
{
    extern __shared__ __align__(16) __half smh[];
    uint32_t sbase = smem_u32(smh);
    const uint32_t* S32 = (const uint32_t*)smh;
    int tid = threadIdx.x, lane = tid & 31, w = tid >> 5;
    int gid = lane >> 2, tig = lane & 3;
    int wm0 = (w & 3) * 32, wn0 = (w >> 2) * 64;
    int m0 = blockIdx.y * 128, n0 = blockIdx.x * 128;

    float c[2][8][4];
#pragma unroll
    for (int i = 0; i < 2; i++)
#pragma unroll
        for (int j = 0; j < 8; j++)
#pragma unroll
            for (int e = 0; e < 4; e++) c[i][j][e] = 0.0f;

    int nch = K >> 6;
    auto load = [&](int ch, int s) {
        int k0 = ch * 64;
#pragma unroll
        for (int i = 0; i < 4; i++) {
            int qd = tid + i * 256;
            int row = qd >> 3, c8 = qd & 7;
            int mg = (m0 + row < M) ? m0 + row : M - 1;
            cp16(sbase + (uint32_t)(s * 9216 + row * 72 + c8 * 8) * 2,
                 A + (size_t)mg * K + k0 + c8 * 8, (m0 + row < M) ? 16 : 0);
        }
#pragma unroll
        for (int i = 0; i < 4; i++) {
            int qd = tid + i * 256;
            int row = qd >> 3, c8 = qd & 7;
            cp16(sbase + (uint32_t)(18432 + s * 9216 + row * 72 + c8 * 8) * 2,
                 Bw + (size_t)(n0 + row) * K + k0 + c8 * 8, 16);
        }
        CP_COMMIT;
    };

    load(0, 0);
    for (int ch = 0; ch < nch; ch++) {
        int s = ch & 1;
        CP_WAIT0;
        __syncthreads();
        if (ch + 1 < nch) load(ch + 1, s ^ 1);
        const uint32_t* As32 = S32 + s * 4608;
        const uint32_t* Bs32 = S32 + 9216 + s * 4608;
#pragma unroll
        for (int ks = 0; ks < 4; ks++) {
            uint32_t a[2][4], b[8][2];
#pragma unroll
            for (int mt = 0; mt < 2; mt++) {
                int base = (wm0 + mt * 16 + gid) * 36 + ks * 8 + tig;
                a[mt][0] = As32[base];
                a[mt][1] = As32[base + 288];    // +8 rows
                a[mt][2] = As32[base + 4];
                a[mt][3] = As32[base + 292];
            }
#pragma unroll
            for (int nt = 0; nt < 8; nt++) {
                int bidx = (wn0 + nt * 8 + gid) * 36 + ks * 8 + tig;
                b[nt][0] = Bs32[bidx];
                b[nt][1] = Bs32[bidx + 4];
            }
#pragma unroll
            for (int mt = 0; mt < 2; mt++)
#pragma unroll
                for (int nt = 0; nt < 8; nt++)
                    mma16(c[mt][nt], a[mt], b[nt][0], b[nt][1]);
        }
        __syncthreads();
    }

#pragma unroll
    for (int mt = 0; mt < 2; mt++) {
#pragma unroll
        for (int nt = 0; nt < 8; nt++) {
            int col = n0 + wn0 + nt * 8 + tig * 2;
            float b0 = bias[col], b1 = bias[col + 1];
#pragma unroll
            for (int h2 = 0; h2 < 2; h2++) {
                int row = m0 + wm0 + mt * 16 + gid + h2 * 8;
                if (row >= M) continue;
                float v0 = c[mt][nt][h2 * 2] + b0;
                float v1 = c[mt][nt][h2 * 2 + 1] + b1;
                Tout* cp_ = C + (size_t)row * N + col;
                if (EPI == 1) {
                    float2 old = *(float2*)cp_;
                    *(float2*)cp_ = make_float2(v0 + old.x, v1 + old.y);
                } else {
                    if (EPI == 2) { v0 = gelu_f(v0); v1 = gelu_f(v1); }
                    *(__half2*)cp_ = __floats2half2_rn(v0, v1);
                }
            }
        }
    }
}

// ------------------------- flash attention (fp16) ----------------------------
// Per block: one (bh, 128-row q tile). K/V chunks of 128 keys, double-buffered.
// smem halves: K[2][128*72], V[2][128*72] = 73728 B
#define FA_SMEM (4*128*72*2)
#define NCHK 9

__global__ void __launch_bounds__(256)
flash_attn(const __half* __restrict__ qkv, __half* __restrict__ out)
{
    extern __shared__ __align__(16) __half smh[];
    uint32_t sbase = smem_u32(smh);
    const uint32_t* S32 = (const uint32_t*)smh;
    int tid = threadIdx.x, lane = tid & 31, w = tid >> 5;
    int gid = lane >> 2, tig = lane & 3;
    int bh = blockIdx.y, bi = bh / NHH, hd = bh % NHH;
    int m0 = blockIdx.x * 128;
    int wm0 = w * 16;

    // ---- Q fragments, pre-scaled by 1/8 ----
    uint32_t qa[4][4];
    {
        int r0 = m0 + wm0 + gid, r1 = r0 + 8;
        const __half* q0 = qkv + (size_t)(bi * SS + (r0 < SS ? r0 : 0)) * QKVN + hd * 64;
        const __half* q1 = qkv + (size_t)(bi * SS + (r1 < SS ? r1 : 0)) * QKVN + hd * 64;
        __half2 s0 = __float2half2_rn((r0 < SS) ? 0.125f : 0.0f);
        __half2 s1 = __float2half2_rn((r1 < SS) ? 0.125f : 0.0f);
#pragma unroll
        for (int ks = 0; ks < 4; ks++) {
            __half2 t;
            t = __hmul2(*(const __half2*)(q0 + ks * 16 + tig * 2), s0);     qa[ks][0] = *(uint32_t*)&t;
            t = __hmul2(*(const __half2*)(q1 + ks * 16 + tig * 2), s1);     qa[ks][1] = *(uint32_t*)&t;
            t = __hmul2(*(const __half2*)(q0 + ks * 16 + 8 + tig * 2), s0); qa[ks][2] = *(uint32_t*)&t;
            t = __hmul2(*(const __half2*)(q1 + ks * 16 + 8 + tig * 2), s1); qa[ks][3] = *(uint32_t*)&t;
        }
    }

    float o[8][4];
#pragma unroll
    for (int i = 0; i < 8; i++)
#pragma unroll
        for (int e = 0; e < 4; e++) o[i][e] = 0.0f;
    float m_run[2] = {-1e30f, -1e30f};
    float l_run[2] = {0.0f, 0.0f};

    auto loadKV = [&](int c, int s) {
        int jb = c * 128;
#pragma unroll
        for (int i = 0; i < 4; i++) {
            int qd = tid + i * 256;
            int row = qd >> 3, c8 = qd & 7;
            int j = jb + row;
            const __half* src = qkv + (size_t)(bi * SS + (j < SS ? j : 0)) * QKVN
                              + 384 + hd * 64 + c8 * 8;
            cp16(sbase + (uint32_t)(s * 9216 + row * 72 + c8 * 8) * 2, src,
                 (j < SS) ? 16 : 0);
        }
#pragma unroll
        for (int i = 0; i < 4; i++) {
            int qd = tid + i * 256;
            int row = qd >> 3, c8 = qd & 7;
            int j = jb + row;
            const __half* src = qkv + (size_t)(bi * SS + (j < SS ? j : 0)) * QKVN
                              + 768 + hd * 64 + c8 * 8;
            cp16(sbase + (uint32_t)(18432 + s * 9216 + row * 72 + c8 * 8) * 2, src,
                 (j < SS) ? 16 : 0);
        }
        CP_COMMIT;
    };

    loadKV(0, 0);
    loadKV(1, 1);

    for (int c = 0; c < NCHK; c++) {
        int s = c & 1;
        if (c == NCHK - 1) { CP_WAIT0; } else { CP_WAIT1; }
        __syncthreads();
        const uint32_t* Ks32 = S32 + s * 4608;
        uint32_t vbase = sbase + (uint32_t)(18432 + s * 9216) * 2;

        // ---- scores: QK^T (16 rows x 128 cols per warp) ----
        float sc[16][4];
#pragma unroll
        for (int i = 0; i < 16; i++)
#pragma unroll
            for (int e = 0; e < 4; e++) sc[i][e] = 0.0f;
#pragma unroll
        for (int ks = 0; ks < 4; ks++) {
#pragma unroll
            for (int nt = 0; nt < 16; nt++) {
                int bidx = (nt * 8 + gid) * 36 + ks * 8 + tig;
                mma16(sc[nt], qa[ks], Ks32[bidx], Ks32[bidx + 4]);
            }
        }

        // ---- mask invalid columns ----
        int jb = c * 128;
        if (jb + 128 > SS) {
#pragma unroll
            for (int nt = 0; nt < 16; nt++) {
                int j0 = jb + nt * 8 + tig * 2;
                if (j0 >= SS)     { sc[nt][0] = -1e30f; sc[nt][2] = -1e30f; }
                if (j0 + 1 >= SS) { sc[nt][1] = -1e30f; sc[nt][3] = -1e30f; }
            }
        }

        // ---- online softmax ----
#pragma unroll
        for (int h2 = 0; h2 < 2; h2++) {
            float mx = -1e30f;
#pragma unroll
            for (int nt = 0; nt < 16; nt++)
                mx = fmaxf(mx, fmaxf(sc[nt][h2 * 2], sc[nt][h2 * 2 + 1]));
            mx = fmaxf(mx, __shfl_xor_sync(0xffffffffu, mx, 1));
            mx = fmaxf(mx, __shfl_xor_sync(0xffffffffu, mx, 2));
            float mnew = fmaxf(m_run[h2], mx);
            float corr = __expf(m_run[h2] - mnew);
            m_run[h2] = mnew;
            float rs = 0.0f;
#pragma unroll
            for (int nt = 0; nt < 16; nt++) {
                float p0 = __expf(sc[nt][h2 * 2] - mnew);
                float p1 = __expf(sc[nt][h2 * 2 + 1] - mnew);
                sc[nt][h2 * 2] = p0; sc[nt][h2 * 2 + 1] = p1;
                rs += p0 + p1;
            }
            rs += __shfl_xor_sync(0xffffffffu, rs, 1);
            rs += __shfl_xor_sync(0xffffffffu, rs, 2);
            l_run[h2] = l_run[h2] * corr + rs;
#pragma unroll
            for (int ng = 0; ng < 8; ng++) {
                o[ng][h2 * 2] *= corr;
                o[ng][h2 * 2 + 1] *= corr;
            }
        }

        // ---- PV: P(16x128) @ V(128x64); P packs directly into A-frags ----
        int lrow = ((lane >> 3) & 1) * 8 + (lane & 7);
        int lcol = (lane >> 4) * 8;
#pragma unroll
        for (int ks = 0; ks < 8; ks++) {
            uint32_t pa[4];
            __half2 t;
            t = __floats2half2_rn(sc[2*ks][0],   sc[2*ks][1]);   pa[0] = *(uint32_t*)&t;
            t = __floats2half2_rn(sc[2*ks][2],   sc[2*ks][3]);   pa[1] = *(uint32_t*)&t;
            t = __floats2half2_rn(sc[2*ks+1][0], sc[2*ks+1][1]); pa[2] = *(uint32_t*)&t;
            t = __floats2half2_rn(sc[2*ks+1][2], sc[2*ks+1][3]); pa[3] = *(uint32_t*)&t;
#pragma unroll
            for (int np = 0; np < 4; np++) {
                uint32_t r0, r1, r2, r3;
                uint32_t addr = vbase
                    + (uint32_t)((ks * 16 + lrow) * 72 + np * 16 + lcol) * 2;
                ldmx4t(r0, r1, r2, r3, addr);
                mma16(o[np * 2],     pa, r0, r1);
                mma16(o[np * 2 + 1], pa, r2, r3);
            }
        }

        __syncthreads();
        if (c + 2 < NCHK) loadKV(c + 2, s);
    }

    // ---- epilogue ----
#pragma unroll
    for (int h2 = 0; h2 < 2; h2++) {
        int i = m0 + wm0 + gid + h2 * 8;
        if (i >= SS) continue;
        float invl = 1.0f / l_run[h2];
        __half* op = out + (size_t)(bi * SS + i) * HH + hd * 64;
#pragma unroll
        for (int ng = 0; ng < 8; ng++) {
            int d = ng * 8 + tig * 2;
            *(__half2*)(op + d) = __floats2half2_rn(o[ng][h2 * 2] * invl,
                                                    o[ng][h2 * 2 + 1] * invl);
        }
    }
}

// -------------------------- weight prep -------------------------------------
// Transpose+convert: in [L][K][N] f32 -> out [L][rowOff+N][K] fp16
__global__ void transcvt(const float* __restrict__ in, __half* __restrict__ out,
                         int K, int N, size_t outLayerStride, int rowOff)
{
    __shared__ float tile[32][33];
    int l = blockIdx.z;
    int k0 = blockIdx.y * 32, n0 = blockIdx.x * 32;
    const float* ip = in + (size_t)l * K * N;
    __half* op = out + (size_t)l * outLayerStride + (size_t)rowOff * K;
    int tx = threadIdx.x, ty = threadIdx.y;
#pragma unroll
    for (int i = 0; i < 32; i += 8)
        tile[ty + i][tx] = ip[(size_t)(k0 + ty + i) * N + n0 + tx];
    __syncthreads();
#pragma unroll
    for (int i = 0; i < 32; i += 8)
        op[(size_t)(n0 + ty + i) * K + k0 + tx] = __float2half(tile[tx][ty + i]);
}

__global__ void pack_qkv_b(const float* __restrict__ bq,
                           const float* __restrict__ bk,
                           const float* __restrict__ bv,
                           float* __restrict__ out)
{
    int idx = blockIdx.x * 256 + threadIdx.x;
    if (idx >= LL * QKVN) return;
    int n = idx % QKVN;
    int l = idx / QKVN;
    const float* src = (n < HH) ? bq : (n < 2 * HH) ? bk : bv;
    out[idx] = src[l * HH + n % HH];
}

// --------------------------- patch embed (SIMT) -----------------------------
__global__ void patch_embed_kernel(const float* __restrict__ x,
                                   const float* __restrict__ cw,
                                   const float* __restrict__ cb,
                                   const float* __restrict__ pos,
                                   float* __restrict__ h)
{
    __shared__ __align__(16) float As[16][68];
    __shared__ __align__(16) float Bs[16][68];
    int tx = threadIdx.x, ty = threadIdx.y;
    int t = ty * 16 + tx;
    int n0 = blockIdx.x * 64;
    int m0 = blockIdx.y * 64;
    float acc[4][4] = {};

    for (int k0 = 0; k0 < 768; k0 += 16) {
#pragma unroll
        for (int r = 0; r < 4; r++) {
            int idx = t + r * 256;
            int m = idx >> 4, kk = idx & 15;
            int k = k0 + kk;
            int mg = m0 + m;
            int b = mg >> 10, pi = mg & 1023;
            int i = pi >> 5, j = pi & 31;
            int c = k >> 8, rr = (k >> 4) & 15, qq = k & 15;
            As[kk][m] = x[((b * 3 + c) * 512 + i * 16 + rr) * 512 + j * 16 + qq];
            Bs[kk][m] = cw[(n0 + m) * 768 + k];
        }
        __syncthreads();
#pragma unroll
        for (int kk = 0; kk < 16; kk++) {
            float4 af = *(const float4*)(&As[kk][ty * 4]);
            float4 bf = *(const float4*)(&Bs[kk][tx * 4]);
            float av[4] = {af.x, af.y, af.z, af.w};
            float bv[4] = {bf.x, bf.y, bf.z, bf.w};
#pragma unroll
            for (int i = 0; i < 4; i++)
#pragma unroll
                for (int j = 0; j < 4; j++) acc[i][j] += av[i] * bv[j];
        }
        __syncthreads();
    }
#pragma unroll
    for (int i = 0; i < 4; i++) {
        int mg = m0 + ty * 4 + i;
        int b = mg >> 10, pi = mg & 1023;
        int row = b * SS + 1 + pi;
#pragma unroll
        for (int j = 0; j < 4; j++) {
            int o = n0 + tx * 4 + j;
            h[row * HH + o] = acc[i][j] + cb[o] + pos[(1 + pi) * HH + o];
        }
    }
}

__global__ void cls_pos_kernel(const float* __restrict__ cls,
                               const float* __restrict__ pos,
                               float* __restrict__ h)
{
    int t = blockIdx.x * 256 + threadIdx.x;
    if (t < BB * HH) {
        int b = t / HH, o = t % HH;
        h[(b * SS) * HH + o] = cls[o] + pos[o];
    }
}

// --------------------------- LayerNorm (fp16 out) ---------------------------
__global__ void ln_kernel(const float* __restrict__ in,
                          const float* __restrict__ w,
                          const float* __restrict__ b,
                          __half* __restrict__ out)
{
    int row = blockIdx.x;
    const float* p = in + (size_t)row * HH;
    int t = threadIdx.x;            // 128 threads
    float v0 = p[t], v1 = p[t + 128], v2 = p[t + 256];

    __shared__ float sh[4];
    float s = v0 + v1 + v2;
#pragma unroll
    for (int o = 16; o; o >>= 1) s += __shfl_xor_sync(0xffffffffu, s, o);
    if ((t & 31) == 0) sh[t >> 5] = s;
    __syncthreads();
    float mu = (sh[0] + sh[1] + sh[2] + sh[3]) * (1.0f / 384.0f);
    __syncthreads();

    float d0 = v0 - mu, d1 = v1 - mu, d2 = v2 - mu;
    float sq = d0 * d0 + d1 * d1 + d2 * d2;
#pragma unroll
    for (int o = 16; o; o >>= 1) sq += __shfl_xor_sync(0xffffffffu, sq, o);
    if ((t & 31) == 0) sh[t >> 5] = sq;
    __syncthreads();
    float var = (sh[0] + sh[1] + sh[2] + sh[3]) * (1.0f / 384.0f);
    float inv = rsqrtf(var + 1e-5f);

    __half* q = out + (size_t)row * HH;
    q[t]       = __float2half(d0 * inv * w[t]       + b[t]);
    q[t + 128] = __float2half(d1 * inv * w[t + 128] + b[t + 128]);
    q[t + 256] = __float2half(d2 * inv * w[t + 256] + b[t + 256]);
}

// ------------------------------- classifier ---------------------------------
__global__ void classifier_kernel(const float* __restrict__ h,
                                  const float* __restrict__ wc,
                                  const float* __restrict__ bc,
                                  float* __restrict__ out)
{
    int t = blockIdx.x * 256 + threadIdx.x;
    if (t >= BB * NCC) return;
    int b = t / NCC, n = t % NCC;
    const float* hp = h + (size_t)(b * SS) * HH;
    float acc = 0.0f;
    for (int k = 0; k < HH; k++) acc += hp[k] * wc[(size_t)k * NCC + n];
    out[t] = acc + bc[n];
}

// ------------------------------- host side ----------------------------------
extern "C" void kernel_launch(void* const* d_in, const int* in_sizes, int n_in,
                              void* d_out, int out_size)
{
    const float* x    = (const float*)d_in[0];
    const float* cw   = (const float*)d_in[1];
    const float* cb   = (const float*)d_in[2];
    const float* cls  = (const float*)d_in[3];
    const float* pos  = (const float*)d_in[4];
    const float* ln1w = (const float*)d_in[5];
    const float* ln1b = (const float*)d_in[6];
    const float* wq   = (const float*)d_in[7];
    const float* bq   = (const float*)d_in[8];
    const float* wk   = (const float*)d_in[9];
    const float* bk   = (const float*)d_in[10];
    const float* wv   = (const float*)d_in[11];
    const float* bv   = (const float*)d_in[12];
    const float* wo   = (const float*)d_in[13];
    const float* bo   = (const float*)d_in[14];
    const float* ln2w = (const float*)d_in[15];
    const float* ln2b = (const float*)d_in[16];
    const float* w1   = (const float*)d_in[17];
    const float* b1   = (const float*)d_in[18];
    const float* w2   = (const float*)d_in[19];
    const float* b2   = (const float*)d_in[20];
    const float* wc   = (const float*)d_in[21];
    const float* bc   = (const float*)d_in[22];

    float *h; __half *hn, *qkv, *attn, *mlp;
    __half *wqkv, *wot, *w1t, *w2t; float *bqkv;
    cudaGetSymbolAddress((void**)&h,    g_h);
    cudaGetSymbolAddress((void**)&hn,   g_hn);
    cudaGetSymbolAddress((void**)&qkv,  g_qkv);
    cudaGetSymbolAddress((void**)&attn, g_attn);
    cudaGetSymbolAddress((void**)&mlp,  g_mlp);
    cudaGetSymbolAddress((void**)&wqkv, g_wqkv);
    cudaGetSymbolAddress((void**)&bqkv, g_bqkv);
    cudaGetSymbolAddress((void**)&wot,  g_wot);
    cudaGetSymbolAddress((void**)&w1t,  g_w1t);
    cudaGetSymbolAddress((void**)&w2t,  g_w2t);

    // weight prep: transpose+convert to [N][K] fp16
    {
        dim3 tb(32, 8);
        transcvt<<<dim3(HH/32, HH/32, LL), tb>>>(wq, wqkv, HH, HH, (size_t)QKVN*HH, 0);
        transcvt<<<dim3(HH/32, HH/32, LL), tb>>>(wk, wqkv, HH, HH, (size_t)QKVN*HH, HH);
        transcvt<<<dim3(HH/32, HH/32, LL), tb>>>(wv, wqkv, HH, HH, (size_t)QKVN*HH, 2*HH);
        transcvt<<<dim3(HH/32, HH/32, LL), tb>>>(wo, wot, HH, HH, (size_t)HH*HH, 0);
        transcvt<<<dim3(II/32, HH/32, LL), tb>>>(w1, w1t, HH, II, (size_t)II*HH, 0);
        transcvt<<<dim3(HH/32, II/32, LL), tb>>>(w2, w2t, II, HH, (size_t)HH*II, 0);
        pack_qkv_b<<<(LL*QKVN + 255)/256, 256>>>(bq, bk, bv, bqkv);
    }

    cudaFuncSetAttribute((const void*)mma_gemm<0, __half>, cudaFuncAttributeMaxDynamicSharedMemorySize, DG_SMEM);
    cudaFuncSetAttribute((const void*)mma_gemm<1, float>,  cudaFuncAttributeMaxDynamicSharedMemorySize, DG_SMEM);
    cudaFuncSetAttribute((const void*)mma_gemm<2, __half>, cudaFuncAttributeMaxDynamicSharedMemorySize, DG_SMEM);
    cudaFuncSetAttribute((const void*)flash_attn, cudaFuncAttributeMaxDynamicSharedMemorySize, FA_SMEM);

    dim3 blk(16, 16);
    patch_embed_kernel<<<dim3(HH / 64, MPATCH / 64), blk>>>(x, cw, cb, pos, h);
    cls_pos_kernel<<<(BB * HH + 255) / 256, 256>>>(cls, pos, h);

    int mt = (MTOK + 127) / 128;                 // 129
    dim3 gQKV(QKVN / 128, mt);                   // (9, 129)
    dim3 g384(HH / 128, mt);                     // (3, 129)
    dim3 g1536(II / 128, mt);                    // (12, 129)
    dim3 gFA((SS + 127) / 128, BB * NHH);        // (9, 96)

    for (int l = 0; l < LL; l++) {
        ln_kernel<<<MTOK, 128>>>(h, ln1w + l * HH, ln1b + l * HH, hn);
        mma_gemm<0, __half><<<gQKV, 256, DG_SMEM>>>(hn, wqkv + (size_t)l * QKVN * HH,
                                                    bqkv + l * QKVN, qkv, MTOK, QKVN, HH);
        flash_attn<<<gFA, 256, FA_SMEM>>>(qkv, attn);
        mma_gemm<1, float><<<g384, 256, DG_SMEM>>>(attn, wot + (size_t)l * HH * HH,
                                                   bo + l * HH, h, MTOK, HH, HH);
        ln_kernel<<<MTOK, 128>>>(h, ln2w + l * HH, ln2b + l * HH, hn);
        mma_gemm<2, __half><<<g1536, 256, DG_SMEM>>>(hn, w1t + (size_t)l * II * HH,
                                                     b1 + l * II, mlp, MTOK, II, HH);
        mma_gemm<1, float><<<g384, 256, DG_SMEM>>>(mlp, w2t + (size_t)l * HH * II,
                                                   b2 + l * HH, h, MTOK, HH, II);
    }

    classifier_kernel<<<(BB * NCC + 255) / 256, 256>>>(h, wc, bc, (float*)d_out);
}